// round 14
// baseline (speedup 1.0000x reference)
#include <cuda_runtime.h>
#include <math.h>
#include <stdint.h>

#define NN 10000
#define NE 160000
#define HH 8
#define CPD 240
#define EPSLN 1e-5f
#define INV_SQRT2  0.70710678118654752f
#define INV_SQRT3  0.57735026918962576f
#define INV_SQRT32 0.17677669529663689f
#define INV_SQRT48 0.14433756729740643f
#define F_QK0 (1.0f/48.0f)
#define F_QK1 0.018042195912175804f
#define INV16 0.0625f
#define INV_SQRT128 0.08838834764831845f
#define GRID_CSR 296

__device__ float g_SD[NN*160];
__device__ __align__(16) float g_Q[(size_t)NN*640];       // q0[256] | q1[384]
__device__ __align__(16) float g_QK[(size_t)NN*HH*CPD];   // [n][j<240][h<8]
__device__ __align__(16) float g_CP[(size_t)NE*256];      // dst-slot order
__device__ float g_LG[(size_t)NE*8];                      // dst-slot order
__device__ int   g_CNTS[NN], g_CNTD[NN];
__device__ int   g_OFFS[NN+1], g_OFFD[NN+1];
__device__ int   g_CURS[NN], g_CURD[NN];
__device__ int   g_SEID[NE];
__device__ int   g_POS[NE];
__device__ __align__(16) float g_MSG[NN*640];
__device__ __align__(16) float g_W0T[256*48];    // key half Wkv0, [col][c]
__device__ __align__(16) float g_W1T[128*64];    // key half Wkv1, [col][u]
__device__ __align__(16) float g_Wm0P[256*64];   // [i][lane][{a0,a1}]
__device__ int   g_barA, g_barB, g_barC, g_barD;

__device__ __forceinline__ float warp_sum(float v) {
    #pragma unroll
    for (int o = 16; o; o >>= 1) v += __shfl_xor_sync(0xffffffffu, v, o);
    return v;
}
__device__ __forceinline__ void fma4(float4& a, float s, const float4 w) {
    a.x = fmaf(s, w.x, a.x); a.y = fmaf(s, w.y, a.y);
    a.z = fmaf(s, w.z, a.z); a.w = fmaf(s, w.w, a.w);
}
__device__ __forceinline__ void grid_bar(int* bar, int target) {
    __syncthreads();
    if (threadIdx.x == 0) {
        __threadfence();
        atomicAdd(bar, 1);
        while (*(volatile int*)bar < target) { }
    }
    __syncthreads();
    __threadfence();
}

__global__ void k_nop() { }

// fused: weight transposes + zero counters -> histogram -> dual scan -> bucket
__global__ void k_csr(const int* __restrict__ ei,
                      const float* __restrict__ Wkv0, const float* __restrict__ Wkv1,
                      const float* __restrict__ Wm0) {
    int tid = threadIdx.x;
    int gtid = blockIdx.x * 256 + tid;

    for (int t = gtid; t < 12288; t += GRID_CSR*256) {
        int c = t / 256, col = t % 256;
        g_W0T[col*48 + c] = Wkv0[c*512 + col];
    }
    for (int t = gtid; t < 8192; t += GRID_CSR*256) {
        int u = t / 128, col = t % 128;
        g_W1T[col*64 + u] = Wkv1[u*256 + col];
    }
    for (int t = gtid; t < 16384; t += GRID_CSR*256) {
        int i = t / 64, r = t % 64, ln = r / 2, sel = r % 2;
        g_Wm0P[t] = Wm0[i*64 + (sel ? 32 + ln : ln)];
    }

    for (int i = gtid; i < NN; i += GRID_CSR*256) { g_CNTS[i] = 0; g_CNTD[i] = 0; }
    grid_bar(&g_barA, GRID_CSR);

    for (int e = gtid; e < NE; e += GRID_CSR*256) {
        atomicAdd(&g_CNTS[__ldg(&ei[e])], 1);
        atomicAdd(&g_CNTD[__ldg(&ei[NE + e])], 1);
    }
    grid_bar(&g_barB, GRID_CSR);

    if (blockIdx.x < 2) {
        const int* cnt = (blockIdx.x == 0) ? g_CNTS : g_CNTD;
        int* off = (blockIdx.x == 0) ? g_OFFS : g_OFFD;
        int* cur = (blockIdx.x == 0) ? g_CURS : g_CURD;
        __shared__ int swt[8], swe[8];
        int w = tid >> 5, l = tid & 31;
        int base = tid * 40;
        int loc[40];
        int s = 0;
        #pragma unroll
        for (int i = 0; i < 40; i++) {
            int idx = base + i;
            int c = (idx < NN) ? cnt[idx] : 0;
            loc[i] = s; s += c;
        }
        int incl = s;
        #pragma unroll
        for (int o = 1; o < 32; o <<= 1) {
            int v = __shfl_up_sync(0xffffffffu, incl, o);
            if (l >= o) incl += v;
        }
        if (l == 31) swt[w] = incl;
        __syncthreads();
        if (w == 0) {
            int v = (l < 8) ? swt[l] : 0;
            int iv = v;
            #pragma unroll
            for (int o = 1; o < 8; o <<= 1) {
                int u = __shfl_up_sync(0xffffffffu, iv, o);
                if (l >= o) iv += u;
            }
            if (l < 8) swe[l] = iv - v;
        }
        __syncthreads();
        int excl = incl - s + swe[w];
        #pragma unroll
        for (int i = 0; i < 40; i++) {
            int idx = base + i;
            if (idx < NN) { int o2 = excl + loc[i]; off[idx] = o2; cur[idx] = o2; }
        }
        if (tid == 255) off[NN] = excl + s;
    }
    grid_bar(&g_barC, GRID_CSR);

    for (int e = gtid; e < NE; e += GRID_CSR*256) {
        int src = __ldg(&ei[e]), dst = __ldg(&ei[NE + e]);
        g_SEID[atomicAdd(&g_CURS[src], 1)] = e;
        g_POS[e] = atomicAdd(&g_CURD[dst], 1);
    }
    __syncthreads();
    if (tid == 0) {
        __threadfence();
        int old = atomicAdd(&g_barD, 1);
        if (old == GRID_CSR - 1) { g_barA = 0; g_barB = 0; g_barC = 0; g_barD = 0; }
    }
}

// phase A: layernorm + s/d + q (weights ~100KB, L1-resident); node pair per warp
__global__ void __launch_bounds__(256, 4)
k_nodeA(const float* __restrict__ node,
        const float* __restrict__ g0, const float* __restrict__ g1,
        const float* __restrict__ Wq0, const float* __restrict__ Wq1,
        const float* __restrict__ Ws0, const float* __restrict__ Ws1,
        const float* __restrict__ Wd0, const float* __restrict__ Wd1) {
    __shared__ float scratch[8][320];
    int warp = threadIdx.x >> 5, lane = threadIdx.x & 31;
    float* h0s = scratch[warp];         // [p][64]
    float* h1s = scratch[warp] + 128;   // [p][96]

    int n0 = blockIdx.x * 16 + warp * 2;

    #pragma unroll
    for (int p = 0; p < 2; p++) {
        int n = n0 + p;
        const float* nr = node + (size_t)n * 160;
        float e0 = nr[lane], e1 = nr[32 + lane];
        float mu = warp_sum(e0 + e1) * (1.0f/64.0f);
        float var = warp_sum((e0-mu)*(e0-mu) + (e1-mu)*(e1-mu)) * (1.0f/64.0f);
        float rs0 = rsqrtf(var + EPSLN);
        h0s[p*64 + lane]    = (e0-mu)*rs0*__ldg(&g0[lane]);
        h0s[p*64 + 32+lane] = (e1-mu)*rs0*__ldg(&g0[32+lane]);
        float t0 = nr[64+lane], t1 = nr[96+lane], t2 = nr[128+lane];
        float vn = warp_sum(t0*t0 + t1*t1 + t2*t2) * (1.0f/32.0f);
        float rs1 = rsqrtf(vn + EPSLN);
        h1s[p*96 + lane]    = t0*rs1*__ldg(&g1[lane/3]);
        h1s[p*96 + 32+lane] = t1*rs1*__ldg(&g1[(32+lane)/3]);
        h1s[p*96 + 64+lane] = t2*rs1*__ldg(&g1[(64+lane)/3]);
    }
    __syncwarp();

    // s0/d0 both nodes
    {
        float a0 = 0.f, b0 = 0.f, a1 = 0.f, b1 = 0.f;
        #pragma unroll
        for (int i = 0; i < 64; i++) {
            float ws = __ldg(&Ws0[i*32 + lane]);
            float wd = __ldg(&Wd0[i*32 + lane]);
            float hA = h0s[i], hB = h0s[64 + i];
            a0 = fmaf(hA, ws, a0); b0 = fmaf(hA, wd, b0);
            a1 = fmaf(hB, ws, a1); b1 = fmaf(hB, wd, b1);
        }
        g_SD[(size_t)n0*160 + lane]          = a0 * 0.125f;
        g_SD[(size_t)n0*160 + 80 + lane]     = b0 * 0.125f;
        g_SD[(size_t)(n0+1)*160 + lane]      = a1 * 0.125f;
        g_SD[(size_t)(n0+1)*160 + 80 + lane] = b1 * 0.125f;
    }
    // s1/d1 both nodes
    #pragma unroll
    for (int rep = 0; rep < 2; rep++) {
        int j = rep*32 + lane;
        if (j < 48) {
            int v_ = j/3, c_ = j%3;
            float a0 = 0.f, b0 = 0.f, a1 = 0.f, b1 = 0.f;
            #pragma unroll
            for (int u = 0; u < 32; u++) {
                float ws = __ldg(&Ws1[u*16 + v_]);
                float wd = __ldg(&Wd1[u*16 + v_]);
                float hA = h1s[u*3 + c_], hB = h1s[96 + u*3 + c_];
                a0 = fmaf(hA, ws, a0); b0 = fmaf(hA, wd, b0);
                a1 = fmaf(hB, ws, a1); b1 = fmaf(hB, wd, b1);
            }
            g_SD[(size_t)n0*160 + 32 + j]       = a0 * INV_SQRT32;
            g_SD[(size_t)n0*160 + 112 + j]      = b0 * INV_SQRT32;
            g_SD[(size_t)(n0+1)*160 + 32 + j]   = a1 * INV_SQRT32;
            g_SD[(size_t)(n0+1)*160 + 112 + j]  = b1 * INV_SQRT32;
        }
    }
    // q0 both nodes -> g_Q
    #pragma unroll
    for (int h = 0; h < 8; h++) {
        float a0 = 0.f, a1 = 0.f;
        #pragma unroll
        for (int i = 0; i < 64; i++) {
            float w = __ldg(&Wq0[i*256 + h*32 + lane]);
            a0 = fmaf(h0s[i], w, a0);
            a1 = fmaf(h0s[64 + i], w, a1);
        }
        g_Q[(size_t)n0*640 + h*32 + lane]     = a0 * 0.125f;
        g_Q[(size_t)(n0+1)*640 + h*32 + lane] = a1 * 0.125f;
    }
    // q1 both nodes -> g_Q (offset 256, layout h*48+v*3+c)
    #pragma unroll
    for (int k = 0; k < 12; k++) {
        int j = k*32 + lane;
        int h = j/48, r = j%48, v_ = r/3, c_ = r%3;
        float a0 = 0.f, a1 = 0.f;
        #pragma unroll
        for (int u = 0; u < 32; u++) {
            float w = __ldg(&Wq1[u*128 + h*16 + v_]);
            a0 = fmaf(h1s[u*3 + c_], w, a0);
            a1 = fmaf(h1s[96 + u*3 + c_], w, a1);
        }
        g_Q[(size_t)n0*640 + 256 + j]     = a0 * INV_SQRT32;
        g_Q[(size_t)(n0+1)*640 + 256 + j] = a1 * INV_SQRT32;
    }
}

// phase B: QK = q projected through key weights (weights 80KB, L1-resident)
__global__ void __launch_bounds__(256, 4)
k_nodeB() {
    __shared__ float qsm[8][1280];
    int warp = threadIdx.x >> 5, lane = threadIdx.x & 31;
    float* q0s = qsm[warp];          // [p][256]
    float* q1s = qsm[warp] + 512;    // [p][384]

    int n0 = blockIdx.x * 16 + warp * 2;

    #pragma unroll
    for (int p = 0; p < 2; p++) {
        const float* qr = g_Q + (size_t)(n0 + p) * 640;
        for (int j = lane; j < 256; j += 32) q0s[p*256 + j] = __ldg(&qr[j]);
        for (int j = lane; j < 384; j += 32) q1s[p*384 + j] = __ldg(&qr[256 + j]);
    }
    __syncwarp();

    float* qk0n = g_QK + (size_t)n0 * (HH*CPD);
    float* qk1n = g_QK + (size_t)(n0+1) * (HH*CPD);
    #pragma unroll
    for (int k = 0; k < 12; k++) {
        int j = k*32 + lane;
        int h = j/48, c = j%48;
        float a0 = 0.f, a1 = 0.f;
        #pragma unroll
        for (int m = 0; m < 32; m++) {
            float w = __ldg(&g_W0T[(h*32+m)*48 + c]);
            a0 = fmaf(q0s[h*32 + m], w, a0);
            a1 = fmaf(q0s[256 + h*32 + m], w, a1);
        }
        qk0n[c*8 + h] = a0 * F_QK0;
        qk1n[c*8 + h] = a1 * F_QK0;
    }
    #pragma unroll
    for (int k = 0; k < 48; k++) {
        int j = k*32 + lane;
        int h = j/192, cart = (j/64)%3, u = j%64;
        float a0 = 0.f, a1 = 0.f;
        #pragma unroll
        for (int v_ = 0; v_ < 16; v_++) {
            float w = __ldg(&g_W1T[(h*16+v_)*64 + u]);
            a0 = fmaf(q1s[h*48 + v_*3 + cart], w, a0);
            a1 = fmaf(q1s[384 + h*48 + v_*3 + cart], w, a1);
        }
        qk0n[(48 + cart*64 + u)*8 + h] = a0 * F_QK1;
        qk1n[(48 + cart*64 + u)*8 + h] = a1 * F_QK1;
    }
}

// build 240-dim tensor-product vector for one edge (warp-cooperative)
__device__ __forceinline__ void build_cp(int e, int src, int dst,
                                         const float* __restrict__ rbf,
                                         const float* __restrict__ rsh,
                                         const float* __restrict__ Ws,
                                         float* wb, float* CP, int lane) {
    float* rb  = wb;
    float* ys  = wb + 16;
    float* x0s = wb + 20;
    float* x1s = wb + 52;
    if (lane < 16) rb[lane] = __ldg(&rbf[(size_t)e*16 + lane]);
    if (lane < 4)  ys[lane] = __ldg(&rsh[(size_t)e*4 + lane]);
    x0s[lane] = __ldg(&g_SD[(size_t)src*160 + lane]) + __ldg(&g_SD[(size_t)dst*160 + 80 + lane]);
    x1s[lane] = __ldg(&g_SD[(size_t)src*160 + 32 + lane]) + __ldg(&g_SD[(size_t)dst*160 + 112 + lane]);
    if (lane < 16)
        x1s[32+lane] = __ldg(&g_SD[(size_t)src*160 + 64 + lane]) + __ldg(&g_SD[(size_t)dst*160 + 144 + lane]);
    __syncwarp();

    float y0 = ys[0], y1x = ys[1], y1y = ys[2], y1z = ys[3];
    #define WCH(J, OUT) { float _a = 0.f; _Pragma("unroll") \
        for (int _k = 0; _k < 16; _k++) _a = fmaf(rb[_k], Ws[_k*112 + (J)], _a); OUT = _a; }

    { float w; WCH(lane, w); CP[lane] = w * x0s[lane] * y0; }
    if (lane < 16) {
        float w; WCH(32 + lane, w);
        float d = x1s[lane*3]*y1x + x1s[lane*3+1]*y1y + x1s[lane*3+2]*y1z;
        CP[32 + lane] = w * d * INV_SQRT3;
    }
    { float w; WCH(48 + lane, w);
      float xv = w * x0s[lane];
      CP[48 + lane]       = xv * y1x;
      CP[48 + 64 + lane]  = xv * y1y;
      CP[48 + 128 + lane] = xv * y1z; }
    if (lane < 16) {
        float w; WCH(80 + lane, w);
        float wy = w * y0;
        CP[48 + 32 + lane]       = wy * x1s[lane*3];
        CP[48 + 64 + 32 + lane]  = wy * x1s[lane*3+1];
        CP[48 + 128 + 32 + lane] = wy * x1s[lane*3+2];
    } else {
        int t = lane - 16;
        float w; WCH(96 + t, w);
        w *= INV_SQRT2;
        float ax = x1s[t*3], ay = x1s[t*3+1], az = x1s[t*3+2];
        CP[48 + 48 + t]       = w * (ay*y1z - az*y1y);
        CP[48 + 64 + 48 + t]  = w * (az*y1x - ax*y1z);
        CP[48 + 128 + 48 + t] = w * (ax*y1y - ay*y1x);
    }
    #undef WCH
    __syncwarp();
}

// per-src-node warp: chunks of 2 out-edges share one pass over QK[src]
__global__ void __launch_bounds__(256, 4)
k_edge(const float* __restrict__ rbf, const float* __restrict__ rsh,
       const int* __restrict__ ei, const float* __restrict__ Wrbf) {
    __shared__ float sW[16*112];
    __shared__ float wbuf[8][112];
    __shared__ __align__(16) float cps[8][480];
    int warp = threadIdx.x >> 5, lane = threadIdx.x & 31;
    for (int i = threadIdx.x; i < 16*112; i += 256) sW[i] = Wrbf[i];
    __syncthreads();

    int n = blockIdx.x * 8 + warp;
    int offs = g_OFFS[n];
    int degS = g_OFFS[n+1] - offs;
    const float* qkb = g_QK + (size_t)n * 1920;
    float* wb = wbuf[warp];
    float* CPB = cps[warp];

    for (int base = 0; base < degS; base += 2) {
        int cnt = min(2, degS - base);
        int eL = 0, slotL = 0;
        if (lane < cnt) { eL = __ldg(&g_SEID[offs + base + lane]); slotL = __ldg(&g_POS[eL]); }
        int ee[2], sl[2];
        #pragma unroll
        for (int i = 0; i < 2; i++) {
            ee[i] = __shfl_sync(0xffffffffu, eL, i);
            sl[i] = __shfl_sync(0xffffffffu, slotL, i);
        }
        for (int i = 0; i < cnt; i++) {
            int e = ee[i];
            int dst = __ldg(&ei[NE + e]);
            build_cp(e, n, dst, rbf, rsh, sW, wb, CPB + i*240, lane);
        }

        float acc[16];
        #pragma unroll
        for (int k = 0; k < 16; k++) acc[k] = 0.f;
        for (int j = lane; j < 240; j += 32) {
            const float4* p = (const float4*)(qkb + j*8);
            float4 qa = __ldg(p), qb = __ldg(p + 1);
            #pragma unroll
            for (int i = 0; i < 2; i++) {
                float cp = CPB[i*240 + j];
                acc[i*8+0] = fmaf(cp, qa.x, acc[i*8+0]);
                acc[i*8+1] = fmaf(cp, qa.y, acc[i*8+1]);
                acc[i*8+2] = fmaf(cp, qa.z, acc[i*8+2]);
                acc[i*8+3] = fmaf(cp, qa.w, acc[i*8+3]);
                acc[i*8+4] = fmaf(cp, qb.x, acc[i*8+4]);
                acc[i*8+5] = fmaf(cp, qb.y, acc[i*8+5]);
                acc[i*8+6] = fmaf(cp, qb.z, acc[i*8+6]);
                acc[i*8+7] = fmaf(cp, qb.w, acc[i*8+7]);
            }
        }
        #pragma unroll
        for (int o = 16; o; o >>= 1)
            #pragma unroll
            for (int k = 0; k < 16; k++) acc[k] += __shfl_xor_sync(0xffffffffu, acc[k], o);

        if (lane == 0) {
            #pragma unroll
            for (int i = 0; i < 2; i++) {
                if (i < cnt) {
                    float4* lg = (float4*)(g_LG + (size_t)sl[i]*8);
                    lg[0] = make_float4(acc[i*8+0], acc[i*8+1], acc[i*8+2], acc[i*8+3]);
                    lg[1] = make_float4(acc[i*8+4], acc[i*8+5], acc[i*8+6], acc[i*8+7]);
                }
            }
        }
        for (int i = 0; i < cnt; i++) {
            float4* dcp = (float4*)(g_CP + (size_t)sl[i]*256);
            const float4* scp = (const float4*)(CPB + i*240);
            dcp[lane] = scp[lane];
            if (lane < 28) dcp[32+lane] = scp[32+lane];
        }
    }
}

// per-node: softmax + attn-weighted CP (4-edge unroll) + value GEMM
__global__ void k_gather(const float* __restrict__ Wkv0, const float* __restrict__ Wkv1) {
    extern __shared__ float sg[];
    float* sWv0 = sg;             // [c<48][j<256]
    float* sWv1 = sg + 12288;     // [u<64][j<128]
    float* sST  = sg + 20480;     // 8 warps x 512
    float* sMZ  = sg + 24576;     // 8 warps x 16

    int warp = threadIdx.x >> 5, lane = threadIdx.x & 31;
    for (int i = threadIdx.x; i < 12288; i += 256) {
        int c = i >> 8, j = i & 255;
        sWv0[i] = Wkv0[c*512 + 256 + j];
    }
    for (int i = threadIdx.x; i < 8192; i += 256) {
        int u = i >> 7, j = i & 127;
        sWv1[i] = Wkv1[u*256 + 128 + j];
    }
    __syncthreads();

    int n = blockIdx.x * 8 + warp;
    int start = g_OFFD[n];
    int deg = g_OFFD[n+1] - start;

    int q = lane >> 3, h = lane & 7;
    float m = -INFINITY;
    for (int i = q; i < deg; i += 4)
        m = fmaxf(m, __ldg(&g_LG[(size_t)(start+i)*8 + h]));
    m = fmaxf(m, __shfl_xor_sync(0xffffffffu, m, 8));
    m = fmaxf(m, __shfl_xor_sync(0xffffffffu, m, 16));
    float z = 0.f;
    for (int i = q; i < deg; i += 4)
        z += __expf(__ldg(&g_LG[(size_t)(start+i)*8 + h]) - m);
    z += __shfl_xor_sync(0xffffffffu, z, 8);
    z += __shfl_xor_sync(0xffffffffu, z, 16);
    float* mz = sMZ + warp*16;
    if (lane < 8) { mz[lane] = m; mz[8 + lane] = 1.f / (z + 1e-16f); }
    __syncwarp();

    float4 aA[8], aB[8];
    #pragma unroll
    for (int hh = 0; hh < 8; hh++) { aA[hh] = make_float4(0,0,0,0); aB[hh] = make_float4(0,0,0,0); }
    for (int i = 0; i < deg; i += 4) {
        int ss[4];
        float att[4] = {0.f, 0.f, 0.f, 0.f};
        #pragma unroll
        for (int k = 0; k < 4; k++) ss[k] = (i + k < deg) ? (start + i + k) : start + i;
        if (lane < 8) {
            att[0] = __expf(__ldg(&g_LG[(size_t)ss[0]*8 + lane]) - mz[lane]) * mz[8 + lane];
            if (i + 1 < deg) att[1] = __expf(__ldg(&g_LG[(size_t)ss[1]*8 + lane]) - mz[lane]) * mz[8 + lane];
            if (i + 2 < deg) att[2] = __expf(__ldg(&g_LG[(size_t)ss[2]*8 + lane]) - mz[lane]) * mz[8 + lane];
            if (i + 3 < deg) att[3] = __expf(__ldg(&g_LG[(size_t)ss[3]*8 + lane]) - mz[lane]) * mz[8 + lane];
        }
        float4 ca[4], cb[4];
        #pragma unroll
        for (int k = 0; k < 4; k++) {
            const float4* cp = (const float4*)(g_CP + (size_t)ss[k]*256);
            ca[k] = __ldg(&cp[lane]);
            cb[k] = (lane < 28) ? __ldg(&cp[32 + lane]) : make_float4(0,0,0,0);
        }
        #pragma unroll
        for (int hh = 0; hh < 8; hh++) {
            #pragma unroll
            for (int k = 0; k < 4; k++) {
                float a = __shfl_sync(0xffffffffu, att[k], hh);
                fma4(aA[hh], a, ca[k]);
                fma4(aB[hh], a, cb[k]);
            }
        }
    }

    float* st = sST + warp*512;
    float* mrow = g_MSG + (size_t)n * 640;
    #pragma unroll
    for (int p = 0; p < 4; p++) {
        int h0 = 2*p, h1 = 2*p + 1;
        ((float4*)st)[lane]      = aA[h0];
        ((float4*)st)[32 + lane] = aB[h0];
        ((float4*)st)[64 + lane] = aA[h1];
        ((float4*)st)[96 + lane] = aB[h1];
        __syncwarp();

        float a0 = 0.f, a1 = 0.f;
        #pragma unroll 4
        for (int c = 0; c < 48; c++) {
            a0 = fmaf(st[c],       sWv0[c*256 + h0*32 + lane], a0);
            a1 = fmaf(st[256 + c], sWv0[c*256 + h1*32 + lane], a1);
        }
        mrow[h0*80 + lane] = a0 * INV_SQRT48;
        mrow[h1*80 + lane] = a1 * INV_SQRT48;

        int hsel = (lane < 16) ? h0 : h1;
        int v_ = lane & 15;
        const float* stv = st + ((lane < 16) ? 0 : 256) + 48;
        float c0 = 0.f, c1 = 0.f, c2 = 0.f;
        #pragma unroll 4
        for (int u = 0; u < 64; u++) {
            float w = sWv1[u*128 + hsel*16 + v_];
            c0 = fmaf(stv[u],       w, c0);
            c1 = fmaf(stv[64 + u],  w, c1);
            c2 = fmaf(stv[128 + u], w, c2);
        }
        mrow[hsel*80 + 32 + v_*3 + 0] = c0 * 0.125f;
        mrow[hsel*80 + 32 + v_*3 + 1] = c1 * 0.125f;
        mrow[hsel*80 + 32 + v_*3 + 2] = c2 * 0.125f;
        __syncwarp();
    }
}

__global__ void k_out(const float* __restrict__ node,
                      const float* __restrict__ Wm1,
                      float* __restrict__ out) {
    __shared__ float msgs_all[8][640];
    int warp = threadIdx.x >> 5, lane = threadIdx.x & 31;
    int n = blockIdx.x * 8 + warp;
    float* msgs = msgs_all[warp];
    for (int j = lane; j < 640; j += 32) msgs[j] = g_MSG[(size_t)n*640 + j];
    __syncwarp();

    const float* nr = node + (size_t)n * 160;
    float* orow = out + (size_t)n * 160;

    float a0 = 0.f, a1 = 0.f;
    #pragma unroll 8
    for (int i = 0; i < 256; i++) {
        float m = msgs[(i >> 5)*80 + (i & 31)];
        float2 w = __ldg((const float2*)(g_Wm0P + i*64 + lane*2));
        a0 = fmaf(m, w.x, a0);
        a1 = fmaf(m, w.y, a1);
    }
    orow[lane]      = nr[lane]      + a0 * INV16;
    orow[32 + lane] = nr[32 + lane] + a1 * INV16;

    float c0 = 0.f, c1 = 0.f, c2 = 0.f;
    #pragma unroll 8
    for (int u = 0; u < 128; u++) {
        int hh = u >> 4, v_ = u & 15;
        float w = __ldg(&Wm1[u*32 + lane]);
        const float* mp = msgs + hh*80 + 32 + v_*3;
        c0 = fmaf(mp[0], w, c0);
        c1 = fmaf(mp[1], w, c1);
        c2 = fmaf(mp[2], w, c2);
    }
    orow[64 + lane*3 + 0] = nr[64 + lane*3 + 0] + c0 * INV_SQRT128;
    orow[64 + lane*3 + 1] = nr[64 + lane*3 + 1] + c1 * INV_SQRT128;
    orow[64 + lane*3 + 2] = nr[64 + lane*3 + 2] + c2 * INV_SQRT128;
}

extern "C" void kernel_launch(void* const* d_in, const int* in_sizes, int n_in,
                              void* d_out, int out_size) {
    const float* node = (const float*)d_in[0];
    const float* rbf  = (const float*)d_in[1];
    const float* rsh  = (const float*)d_in[2];
    const int*   ei   = (const int*)d_in[3];
    const float* g0   = (const float*)d_in[4];
    const float* g1   = (const float*)d_in[5];
    const float* Wq0  = (const float*)d_in[6];
    const float* Wq1  = (const float*)d_in[7];
    const float* Ws0  = (const float*)d_in[8];
    const float* Ws1  = (const float*)d_in[9];
    const float* Wd0  = (const float*)d_in[10];
    const float* Wd1  = (const float*)d_in[11];
    const float* Wrbf = (const float*)d_in[12];
    const float* Wkv0 = (const float*)d_in[13];
    const float* Wkv1 = (const float*)d_in[14];
    const float* Wm0  = (const float*)d_in[15];
    const float* Wm1  = (const float*)d_in[16];
    float* out = (float*)d_out;

    cudaFuncSetAttribute(k_gather, cudaFuncAttributeMaxDynamicSharedMemorySize, 98816);

    k_csr<<<GRID_CSR, 256>>>(ei, Wkv0, Wkv1, Wm0);
    k_nop<<<1, 32>>>();
    k_nodeA<<<NN/16, 256>>>(node, g0, g1, Wq0, Wq1, Ws0, Ws1, Wd0, Wd1);
    k_nodeB<<<NN/16, 256>>>();
    k_edge<<<NN/8, 256>>>(rbf, rsh, ei, Wrbf);
    k_gather<<<NN/8, 256, 98816>>>(Wkv0, Wkv1);
    k_out<<<NN/8, 256>>>(node, Wm1, out);
}

// round 15
// speedup vs baseline: 1.8300x; 1.8300x over previous
#include <cuda_runtime.h>
#include <math.h>
#include <stdint.h>

#define NN 10000
#define NE 160000
#define HH 8
#define CPD 240
#define EPSLN 1e-5f
#define INV_SQRT2  0.70710678118654752f
#define INV_SQRT3  0.57735026918962576f
#define INV_SQRT32 0.17677669529663689f
#define INV_SQRT48 0.14433756729740643f
#define F_QK0 (1.0f/48.0f)
#define F_QK1 0.018042195912175804f
#define INV16 0.0625f
#define INV_SQRT128 0.08838834764831845f
#define GRID_CSR 296

__device__ float g_SD[NN*160];
__device__ __align__(16) float g_QK[(size_t)NN*HH*CPD];   // [n][j<240][h<8]
__device__ __align__(16) float g_CP[(size_t)NE*256];      // dst-slot order
__device__ float g_LG[(size_t)NE*8];                      // dst-slot order
__device__ int   g_CNTS[NN], g_CNTD[NN];
__device__ int   g_OFFS[NN+1], g_OFFD[NN+1];
__device__ int   g_CURS[NN], g_CURD[NN];
__device__ int   g_SEID[NE];
__device__ int   g_POS[NE];
__device__ __align__(16) float g_MSG[NN*640];
__device__ __align__(16) float g_W0T[256*48];    // key half Wkv0, [col][c]
__device__ __align__(16) float g_W1T[128*64];    // key half Wkv1, [col][u]
__device__ __align__(16) float g_Wm0P[256*64];   // [i][lane][{a0,a1}]
__device__ int   g_barA, g_barB, g_barC, g_barD;

__device__ __forceinline__ float warp_sum(float v) {
    #pragma unroll
    for (int o = 16; o; o >>= 1) v += __shfl_xor_sync(0xffffffffu, v, o);
    return v;
}
__device__ __forceinline__ void fma4(float4& a, float s, const float4 w) {
    a.x = fmaf(s, w.x, a.x); a.y = fmaf(s, w.y, a.y);
    a.z = fmaf(s, w.z, a.z); a.w = fmaf(s, w.w, a.w);
}
__device__ __forceinline__ void grid_bar(int* bar, int target) {
    __syncthreads();
    if (threadIdx.x == 0) {
        __threadfence();
        atomicAdd(bar, 1);
        while (*(volatile int*)bar < target) { }
    }
    __syncthreads();
    __threadfence();
}

__global__ void k_nop() { }

// fused: weight transposes + zero counters -> histogram -> dual scan -> bucket
__global__ void k_csr(const int* __restrict__ ei,
                      const float* __restrict__ Wkv0, const float* __restrict__ Wkv1,
                      const float* __restrict__ Wm0) {
    int tid = threadIdx.x;
    int gtid = blockIdx.x * 256 + tid;

    for (int t = gtid; t < 12288; t += GRID_CSR*256) {
        int c = t / 256, col = t % 256;
        g_W0T[col*48 + c] = Wkv0[c*512 + col];
    }
    for (int t = gtid; t < 8192; t += GRID_CSR*256) {
        int u = t / 128, col = t % 128;
        g_W1T[col*64 + u] = Wkv1[u*256 + col];
    }
    for (int t = gtid; t < 16384; t += GRID_CSR*256) {
        int i = t / 64, r = t % 64, ln = r / 2, sel = r % 2;
        g_Wm0P[t] = Wm0[i*64 + (sel ? 32 + ln : ln)];
    }

    for (int i = gtid; i < NN; i += GRID_CSR*256) { g_CNTS[i] = 0; g_CNTD[i] = 0; }
    grid_bar(&g_barA, GRID_CSR);

    for (int e = gtid; e < NE; e += GRID_CSR*256) {
        atomicAdd(&g_CNTS[__ldg(&ei[e])], 1);
        atomicAdd(&g_CNTD[__ldg(&ei[NE + e])], 1);
    }
    grid_bar(&g_barB, GRID_CSR);

    if (blockIdx.x < 2) {
        const int* cnt = (blockIdx.x == 0) ? g_CNTS : g_CNTD;
        int* off = (blockIdx.x == 0) ? g_OFFS : g_OFFD;
        int* cur = (blockIdx.x == 0) ? g_CURS : g_CURD;
        __shared__ int swt[8], swe[8];
        int w = tid >> 5, l = tid & 31;
        int base = tid * 40;
        int loc[40];
        int s = 0;
        #pragma unroll
        for (int i = 0; i < 40; i++) {
            int idx = base + i;
            int c = (idx < NN) ? cnt[idx] : 0;
            loc[i] = s; s += c;
        }
        int incl = s;
        #pragma unroll
        for (int o = 1; o < 32; o <<= 1) {
            int v = __shfl_up_sync(0xffffffffu, incl, o);
            if (l >= o) incl += v;
        }
        if (l == 31) swt[w] = incl;
        __syncthreads();
        if (w == 0) {
            int v = (l < 8) ? swt[l] : 0;
            int iv = v;
            #pragma unroll
            for (int o = 1; o < 8; o <<= 1) {
                int u = __shfl_up_sync(0xffffffffu, iv, o);
                if (l >= o) iv += u;
            }
            if (l < 8) swe[l] = iv - v;
        }
        __syncthreads();
        int excl = incl - s + swe[w];
        #pragma unroll
        for (int i = 0; i < 40; i++) {
            int idx = base + i;
            if (idx < NN) { int o2 = excl + loc[i]; off[idx] = o2; cur[idx] = o2; }
        }
        if (tid == 255) off[NN] = excl + s;
    }
    grid_bar(&g_barC, GRID_CSR);

    for (int e = gtid; e < NE; e += GRID_CSR*256) {
        int src = __ldg(&ei[e]), dst = __ldg(&ei[NE + e]);
        g_SEID[atomicAdd(&g_CURS[src], 1)] = e;
        g_POS[e] = atomicAdd(&g_CURD[dst], 1);
    }
    __syncthreads();
    if (tid == 0) {
        __threadfence();
        int old = atomicAdd(&g_barD, 1);
        if (old == GRID_CSR - 1) { g_barA = 0; g_barB = 0; g_barC = 0; g_barD = 0; }
    }
}

// per-node-pair warp: weights loaded once feed both nodes (R13 proven)
__global__ void __launch_bounds__(256, 3)
k_node(const float* __restrict__ node,
       const float* __restrict__ g0, const float* __restrict__ g1,
       const float* __restrict__ Wq0, const float* __restrict__ Wq1,
       const float* __restrict__ Ws0, const float* __restrict__ Ws1,
       const float* __restrict__ Wd0, const float* __restrict__ Wd1) {
    __shared__ float scratch[8][1600];
    int warp = threadIdx.x >> 5, lane = threadIdx.x & 31;
    float* wb  = scratch[warp];
    float* h0s = wb;          // [p][64]
    float* h1s = wb + 128;    // [p][96]
    float* q0s = wb + 320;    // [p][256]
    float* q1s = wb + 832;    // [p][384]

    int n0 = blockIdx.x * 16 + warp * 2;

    #pragma unroll
    for (int p = 0; p < 2; p++) {
        int n = n0 + p;
        const float* nr = node + (size_t)n * 160;
        float e0 = nr[lane], e1 = nr[32 + lane];
        float mu = warp_sum(e0 + e1) * (1.0f/64.0f);
        float var = warp_sum((e0-mu)*(e0-mu) + (e1-mu)*(e1-mu)) * (1.0f/64.0f);
        float rs0 = rsqrtf(var + EPSLN);
        h0s[p*64 + lane]    = (e0-mu)*rs0*__ldg(&g0[lane]);
        h0s[p*64 + 32+lane] = (e1-mu)*rs0*__ldg(&g0[32+lane]);
        float t0 = nr[64+lane], t1 = nr[96+lane], t2 = nr[128+lane];
        float vn = warp_sum(t0*t0 + t1*t1 + t2*t2) * (1.0f/32.0f);
        float rs1 = rsqrtf(vn + EPSLN);
        h1s[p*96 + lane]    = t0*rs1*__ldg(&g1[lane/3]);
        h1s[p*96 + 32+lane] = t1*rs1*__ldg(&g1[(32+lane)/3]);
        h1s[p*96 + 64+lane] = t2*rs1*__ldg(&g1[(64+lane)/3]);
    }
    __syncwarp();

    {
        float a0 = 0.f, b0 = 0.f, a1 = 0.f, b1 = 0.f;
        #pragma unroll
        for (int i = 0; i < 64; i++) {
            float ws = __ldg(&Ws0[i*32 + lane]);
            float wd = __ldg(&Wd0[i*32 + lane]);
            float hA = h0s[i], hB = h0s[64 + i];
            a0 = fmaf(hA, ws, a0); b0 = fmaf(hA, wd, b0);
            a1 = fmaf(hB, ws, a1); b1 = fmaf(hB, wd, b1);
        }
        g_SD[(size_t)n0*160 + lane]          = a0 * 0.125f;
        g_SD[(size_t)n0*160 + 80 + lane]     = b0 * 0.125f;
        g_SD[(size_t)(n0+1)*160 + lane]      = a1 * 0.125f;
        g_SD[(size_t)(n0+1)*160 + 80 + lane] = b1 * 0.125f;
    }
    #pragma unroll
    for (int rep = 0; rep < 2; rep++) {
        int j = rep*32 + lane;
        if (j < 48) {
            int v_ = j/3, c_ = j%3;
            float a0 = 0.f, b0 = 0.f, a1 = 0.f, b1 = 0.f;
            #pragma unroll
            for (int u = 0; u < 32; u++) {
                float ws = __ldg(&Ws1[u*16 + v_]);
                float wd = __ldg(&Wd1[u*16 + v_]);
                float hA = h1s[u*3 + c_], hB = h1s[96 + u*3 + c_];
                a0 = fmaf(hA, ws, a0); b0 = fmaf(hA, wd, b0);
                a1 = fmaf(hB, ws, a1); b1 = fmaf(hB, wd, b1);
            }
            g_SD[(size_t)n0*160 + 32 + j]       = a0 * INV_SQRT32;
            g_SD[(size_t)n0*160 + 112 + j]      = b0 * INV_SQRT32;
            g_SD[(size_t)(n0+1)*160 + 32 + j]   = a1 * INV_SQRT32;
            g_SD[(size_t)(n0+1)*160 + 112 + j]  = b1 * INV_SQRT32;
        }
    }
    #pragma unroll
    for (int h = 0; h < 8; h++) {
        float a0 = 0.f, a1 = 0.f;
        #pragma unroll
        for (int i = 0; i < 64; i++) {
            float w = __ldg(&Wq0[i*256 + h*32 + lane]);
            a0 = fmaf(h0s[i], w, a0);
            a1 = fmaf(h0s[64 + i], w, a1);
        }
        q0s[h*32 + lane]       = a0 * 0.125f;
        q0s[256 + h*32 + lane] = a1 * 0.125f;
    }
    #pragma unroll
    for (int k = 0; k < 12; k++) {
        int j = k*32 + lane;
        int h = j/48, r = j%48, v_ = r/3, c_ = r%3;
        float a0 = 0.f, a1 = 0.f;
        #pragma unroll
        for (int u = 0; u < 32; u++) {
            float w = __ldg(&Wq1[u*128 + h*16 + v_]);
            a0 = fmaf(h1s[u*3 + c_], w, a0);
            a1 = fmaf(h1s[96 + u*3 + c_], w, a1);
        }
        q1s[j]       = a0 * INV_SQRT32;
        q1s[384 + j] = a1 * INV_SQRT32;
    }
    __syncwarp();

    float* qk0n = g_QK + (size_t)n0 * (HH*CPD);
    float* qk1n = g_QK + (size_t)(n0+1) * (HH*CPD);
    #pragma unroll
    for (int k = 0; k < 12; k++) {
        int j = k*32 + lane;
        int h = j/48, c = j%48;
        float a0 = 0.f, a1 = 0.f;
        #pragma unroll
        for (int m = 0; m < 32; m++) {
            float w = __ldg(&g_W0T[(h*32+m)*48 + c]);
            a0 = fmaf(q0s[h*32 + m], w, a0);
            a1 = fmaf(q0s[256 + h*32 + m], w, a1);
        }
        qk0n[c*8 + h] = a0 * F_QK0;
        qk1n[c*8 + h] = a1 * F_QK0;
    }
    #pragma unroll
    for (int k = 0; k < 48; k++) {
        int j = k*32 + lane;
        int h = j/192, cart = (j/64)%3, u = j%64;
        float a0 = 0.f, a1 = 0.f;
        #pragma unroll
        for (int v_ = 0; v_ < 16; v_++) {
            float w = __ldg(&g_W1T[(h*16+v_)*64 + u]);
            a0 = fmaf(q1s[h*48 + v_*3 + cart], w, a0);
            a1 = fmaf(q1s[384 + h*48 + v_*3 + cart], w, a1);
        }
        qk0n[(48 + cart*64 + u)*8 + h] = a0 * F_QK1;
        qk1n[(48 + cart*64 + u)*8 + h] = a1 * F_QK1;
    }
}

// build 240-dim tensor-product vector for one edge (warp-cooperative)
__device__ __forceinline__ void build_cp(int e, int src, int dst,
                                         const float* __restrict__ rbf,
                                         const float* __restrict__ rsh,
                                         const float* __restrict__ Ws,
                                         float* wb, float* CP, int lane) {
    float* rb  = wb;
    float* ys  = wb + 16;
    float* x0s = wb + 20;
    float* x1s = wb + 52;
    if (lane < 16) rb[lane] = __ldg(&rbf[(size_t)e*16 + lane]);
    if (lane < 4)  ys[lane] = __ldg(&rsh[(size_t)e*4 + lane]);
    x0s[lane] = __ldg(&g_SD[(size_t)src*160 + lane]) + __ldg(&g_SD[(size_t)dst*160 + 80 + lane]);
    x1s[lane] = __ldg(&g_SD[(size_t)src*160 + 32 + lane]) + __ldg(&g_SD[(size_t)dst*160 + 112 + lane]);
    if (lane < 16)
        x1s[32+lane] = __ldg(&g_SD[(size_t)src*160 + 64 + lane]) + __ldg(&g_SD[(size_t)dst*160 + 144 + lane]);
    __syncwarp();

    float y0 = ys[0], y1x = ys[1], y1y = ys[2], y1z = ys[3];
    #define WCH(J, OUT) { float _a = 0.f; _Pragma("unroll") \
        for (int _k = 0; _k < 16; _k++) _a = fmaf(rb[_k], Ws[_k*112 + (J)], _a); OUT = _a; }

    { float w; WCH(lane, w); CP[lane] = w * x0s[lane] * y0; }
    if (lane < 16) {
        float w; WCH(32 + lane, w);
        float d = x1s[lane*3]*y1x + x1s[lane*3+1]*y1y + x1s[lane*3+2]*y1z;
        CP[32 + lane] = w * d * INV_SQRT3;
    }
    { float w; WCH(48 + lane, w);
      float xv = w * x0s[lane];
      CP[48 + lane]       = xv * y1x;
      CP[48 + 64 + lane]  = xv * y1y;
      CP[48 + 128 + lane] = xv * y1z; }
    if (lane < 16) {
        float w; WCH(80 + lane, w);
        float wy = w * y0;
        CP[48 + 32 + lane]       = wy * x1s[lane*3];
        CP[48 + 64 + 32 + lane]  = wy * x1s[lane*3+1];
        CP[48 + 128 + 32 + lane] = wy * x1s[lane*3+2];
    } else {
        int t = lane - 16;
        float w; WCH(96 + t, w);
        w *= INV_SQRT2;
        float ax = x1s[t*3], ay = x1s[t*3+1], az = x1s[t*3+2];
        CP[48 + 48 + t]       = w * (ay*y1z - az*y1y);
        CP[48 + 64 + 48 + t]  = w * (az*y1x - ax*y1z);
        CP[48 + 128 + 48 + t] = w * (ax*y1y - ay*y1x);
    }
    #undef WCH
    __syncwarp();
}

// per-src-node warp: chunks of 2 out-edges share one pass over QK[src];
// lanes read adjacent j-pairs (64B contiguous) to halve L1 wavefronts
__global__ void __launch_bounds__(256, 4)
k_edge(const float* __restrict__ rbf, const float* __restrict__ rsh,
       const int* __restrict__ ei, const float* __restrict__ Wrbf) {
    __shared__ float sW[16*112];
    __shared__ float wbuf[8][112];
    __shared__ __align__(16) float cps[8][480];
    int warp = threadIdx.x >> 5, lane = threadIdx.x & 31;
    for (int i = threadIdx.x; i < 16*112; i += 256) sW[i] = Wrbf[i];
    __syncthreads();

    int n = blockIdx.x * 8 + warp;
    int offs = g_OFFS[n];
    int degS = g_OFFS[n+1] - offs;
    const float* qkb = g_QK + (size_t)n * 1920;
    float* wb = wbuf[warp];
    float* CPB = cps[warp];

    for (int base = 0; base < degS; base += 2) {
        int cnt = min(2, degS - base);
        int eL = 0, slotL = 0;
        if (lane < cnt) { eL = __ldg(&g_SEID[offs + base + lane]); slotL = __ldg(&g_POS[eL]); }
        int ee[2], sl[2];
        #pragma unroll
        for (int i = 0; i < 2; i++) {
            ee[i] = __shfl_sync(0xffffffffu, eL, i);
            sl[i] = __shfl_sync(0xffffffffu, slotL, i);
        }
        for (int i = 0; i < cnt; i++) {
            int e = ee[i];
            int dst = __ldg(&ei[NE + e]);
            build_cp(e, n, dst, rbf, rsh, sW, wb, CPB + i*240, lane);
        }

        float acc[16];
        #pragma unroll
        for (int k = 0; k < 16; k++) acc[k] = 0.f;
        #pragma unroll
        for (int it = 0; it < 4; it++) {
            int j0 = it*64 + 2*lane;
            if (j0 < 240) {
                const float4* p = (const float4*)(qkb + j0*8);
                float4 qa0 = __ldg(p),     qb0 = __ldg(p + 1);
                float4 qa1 = __ldg(p + 2), qb1 = __ldg(p + 3);
                #pragma unroll
                for (int i = 0; i < 2; i++) {
                    float cp0 = CPB[i*240 + j0];
                    float cp1 = CPB[i*240 + j0 + 1];
                    acc[i*8+0] = fmaf(cp0, qa0.x, fmaf(cp1, qa1.x, acc[i*8+0]));
                    acc[i*8+1] = fmaf(cp0, qa0.y, fmaf(cp1, qa1.y, acc[i*8+1]));
                    acc[i*8+2] = fmaf(cp0, qa0.z, fmaf(cp1, qa1.z, acc[i*8+2]));
                    acc[i*8+3] = fmaf(cp0, qa0.w, fmaf(cp1, qa1.w, acc[i*8+3]));
                    acc[i*8+4] = fmaf(cp0, qb0.x, fmaf(cp1, qb1.x, acc[i*8+4]));
                    acc[i*8+5] = fmaf(cp0, qb0.y, fmaf(cp1, qb1.y, acc[i*8+5]));
                    acc[i*8+6] = fmaf(cp0, qb0.z, fmaf(cp1, qb1.z, acc[i*8+6]));
                    acc[i*8+7] = fmaf(cp0, qb0.w, fmaf(cp1, qb1.w, acc[i*8+7]));
                }
            }
        }
        #pragma unroll
        for (int o = 16; o; o >>= 1)
            #pragma unroll
            for (int k = 0; k < 16; k++) acc[k] += __shfl_xor_sync(0xffffffffu, acc[k], o);

        if (lane == 0) {
            #pragma unroll
            for (int i = 0; i < 2; i++) {
                if (i < cnt) {
                    float4* lg = (float4*)(g_LG + (size_t)sl[i]*8);
                    lg[0] = make_float4(acc[i*8+0], acc[i*8+1], acc[i*8+2], acc[i*8+3]);
                    lg[1] = make_float4(acc[i*8+4], acc[i*8+5], acc[i*8+6], acc[i*8+7]);
                }
            }
        }
        for (int i = 0; i < cnt; i++) {
            float4* dcp = (float4*)(g_CP + (size_t)sl[i]*256);
            const float4* scp = (const float4*)(CPB + i*240);
            dcp[lane] = scp[lane];
            if (lane < 28) dcp[32+lane] = scp[32+lane];
        }
    }
}

// per-node: softmax + attn-weighted CP (4-edge unroll) + value GEMM
__global__ void k_gather(const float* __restrict__ Wkv0, const float* __restrict__ Wkv1) {
    extern __shared__ float sg[];
    float* sWv0 = sg;             // [c<48][j<256]
    float* sWv1 = sg + 12288;     // [u<64][j<128]
    float* sST  = sg + 20480;     // 8 warps x 512
    float* sMZ  = sg + 24576;     // 8 warps x 16

    int warp = threadIdx.x >> 5, lane = threadIdx.x & 31;
    for (int i = threadIdx.x; i < 12288; i += 256) {
        int c = i >> 8, j = i & 255;
        sWv0[i] = Wkv0[c*512 + 256 + j];
    }
    for (int i = threadIdx.x; i < 8192; i += 256) {
        int u = i >> 7, j = i & 127;
        sWv1[i] = Wkv1[u*256 + 128 + j];
    }
    __syncthreads();

    int n = blockIdx.x * 8 + warp;
    int start = g_OFFD[n];
    int deg = g_OFFD[n+1] - start;

    int q = lane >> 3, h = lane & 7;
    float m = -INFINITY;
    for (int i = q; i < deg; i += 4)
        m = fmaxf(m, __ldg(&g_LG[(size_t)(start+i)*8 + h]));
    m = fmaxf(m, __shfl_xor_sync(0xffffffffu, m, 8));
    m = fmaxf(m, __shfl_xor_sync(0xffffffffu, m, 16));
    float z = 0.f;
    for (int i = q; i < deg; i += 4)
        z += __expf(__ldg(&g_LG[(size_t)(start+i)*8 + h]) - m);
    z += __shfl_xor_sync(0xffffffffu, z, 8);
    z += __shfl_xor_sync(0xffffffffu, z, 16);
    float* mz = sMZ + warp*16;
    if (lane < 8) { mz[lane] = m; mz[8 + lane] = 1.f / (z + 1e-16f); }
    __syncwarp();

    float4 aA[8], aB[8];
    #pragma unroll
    for (int hh = 0; hh < 8; hh++) { aA[hh] = make_float4(0,0,0,0); aB[hh] = make_float4(0,0,0,0); }
    for (int i = 0; i < deg; i += 4) {
        int ss[4];
        float att[4] = {0.f, 0.f, 0.f, 0.f};
        #pragma unroll
        for (int k = 0; k < 4; k++) ss[k] = (i + k < deg) ? (start + i + k) : start + i;
        if (lane < 8) {
            att[0] = __expf(__ldg(&g_LG[(size_t)ss[0]*8 + lane]) - mz[lane]) * mz[8 + lane];
            if (i + 1 < deg) att[1] = __expf(__ldg(&g_LG[(size_t)ss[1]*8 + lane]) - mz[lane]) * mz[8 + lane];
            if (i + 2 < deg) att[2] = __expf(__ldg(&g_LG[(size_t)ss[2]*8 + lane]) - mz[lane]) * mz[8 + lane];
            if (i + 3 < deg) att[3] = __expf(__ldg(&g_LG[(size_t)ss[3]*8 + lane]) - mz[lane]) * mz[8 + lane];
        }
        float4 ca[4], cb[4];
        #pragma unroll
        for (int k = 0; k < 4; k++) {
            const float4* cp = (const float4*)(g_CP + (size_t)ss[k]*256);
            ca[k] = __ldg(&cp[lane]);
            cb[k] = (lane < 28) ? __ldg(&cp[32 + lane]) : make_float4(0,0,0,0);
        }
        #pragma unroll
        for (int hh = 0; hh < 8; hh++) {
            #pragma unroll
            for (int k = 0; k < 4; k++) {
                float a = __shfl_sync(0xffffffffu, att[k], hh);
                fma4(aA[hh], a, ca[k]);
                fma4(aB[hh], a, cb[k]);
            }
        }
    }

    float* st = sST + warp*512;
    float* mrow = g_MSG + (size_t)n * 640;
    #pragma unroll
    for (int p = 0; p < 4; p++) {
        int h0 = 2*p, h1 = 2*p + 1;
        ((float4*)st)[lane]      = aA[h0];
        ((float4*)st)[32 + lane] = aB[h0];
        ((float4*)st)[64 + lane] = aA[h1];
        ((float4*)st)[96 + lane] = aB[h1];
        __syncwarp();

        float a0 = 0.f, a1 = 0.f;
        #pragma unroll 4
        for (int c = 0; c < 48; c++) {
            a0 = fmaf(st[c],       sWv0[c*256 + h0*32 + lane], a0);
            a1 = fmaf(st[256 + c], sWv0[c*256 + h1*32 + lane], a1);
        }
        mrow[h0*80 + lane] = a0 * INV_SQRT48;
        mrow[h1*80 + lane] = a1 * INV_SQRT48;

        int hsel = (lane < 16) ? h0 : h1;
        int v_ = lane & 15;
        const float* stv = st + ((lane < 16) ? 0 : 256) + 48;
        float c0 = 0.f, c1 = 0.f, c2 = 0.f;
        #pragma unroll 4
        for (int u = 0; u < 64; u++) {
            float w = sWv1[u*128 + hsel*16 + v_];
            c0 = fmaf(stv[u],       w, c0);
            c1 = fmaf(stv[64 + u],  w, c1);
            c2 = fmaf(stv[128 + u], w, c2);
        }
        mrow[hsel*80 + 32 + v_*3 + 0] = c0 * 0.125f;
        mrow[hsel*80 + 32 + v_*3 + 1] = c1 * 0.125f;
        mrow[hsel*80 + 32 + v_*3 + 2] = c2 * 0.125f;
        __syncwarp();
    }
}

__global__ void k_out(const float* __restrict__ node,
                      const float* __restrict__ Wm1,
                      float* __restrict__ out) {
    __shared__ float msgs_all[8][640];
    int warp = threadIdx.x >> 5, lane = threadIdx.x & 31;
    int n = blockIdx.x * 8 + warp;
    float* msgs = msgs_all[warp];
    for (int j = lane; j < 640; j += 32) msgs[j] = g_MSG[(size_t)n*640 + j];
    __syncwarp();

    const float* nr = node + (size_t)n * 160;
    float* orow = out + (size_t)n * 160;

    float a0 = 0.f, a1 = 0.f;
    #pragma unroll 8
    for (int i = 0; i < 256; i++) {
        float m = msgs[(i >> 5)*80 + (i & 31)];
        float2 w = __ldg((const float2*)(g_Wm0P + i*64 + lane*2));
        a0 = fmaf(m, w.x, a0);
        a1 = fmaf(m, w.y, a1);
    }
    orow[lane]      = nr[lane]      + a0 * INV16;
    orow[32 + lane] = nr[32 + lane] + a1 * INV16;

    float c0 = 0.f, c1 = 0.f, c2 = 0.f;
    #pragma unroll 8
    for (int u = 0; u < 128; u++) {
        int hh = u >> 4, v_ = u & 15;
        float w = __ldg(&Wm1[u*32 + lane]);
        const float* mp = msgs + hh*80 + 32 + v_*3;
        c0 = fmaf(mp[0], w, c0);
        c1 = fmaf(mp[1], w, c1);
        c2 = fmaf(mp[2], w, c2);
    }
    orow[64 + lane*3 + 0] = nr[64 + lane*3 + 0] + c0 * INV_SQRT128;
    orow[64 + lane*3 + 1] = nr[64 + lane*3 + 1] + c1 * INV_SQRT128;
    orow[64 + lane*3 + 2] = nr[64 + lane*3 + 2] + c2 * INV_SQRT128;
}

extern "C" void kernel_launch(void* const* d_in, const int* in_sizes, int n_in,
                              void* d_out, int out_size) {
    const float* node = (const float*)d_in[0];
    const float* rbf  = (const float*)d_in[1];
    const float* rsh  = (const float*)d_in[2];
    const int*   ei   = (const int*)d_in[3];
    const float* g0   = (const float*)d_in[4];
    const float* g1   = (const float*)d_in[5];
    const float* Wq0  = (const float*)d_in[6];
    const float* Wq1  = (const float*)d_in[7];
    const float* Ws0  = (const float*)d_in[8];
    const float* Ws1  = (const float*)d_in[9];
    const float* Wd0  = (const float*)d_in[10];
    const float* Wd1  = (const float*)d_in[11];
    const float* Wrbf = (const float*)d_in[12];
    const float* Wkv0 = (const float*)d_in[13];
    const float* Wkv1 = (const float*)d_in[14];
    const float* Wm0  = (const float*)d_in[15];
    const float* Wm1  = (const float*)d_in[16];
    float* out = (float*)d_out;

    cudaFuncSetAttribute(k_gather, cudaFuncAttributeMaxDynamicSharedMemorySize, 98816);

    k_csr<<<GRID_CSR, 256>>>(ei, Wkv0, Wkv1, Wm0);
    k_node<<<NN/16, 256>>>(node, g0, g1, Wq0, Wq1, Ws0, Ws1, Wd0, Wd1);
    k_nop<<<1, 32>>>();
    k_edge<<<NN/8, 256>>>(rbf, rsh, ei, Wrbf);
    k_gather<<<NN/8, 256, 98816>>>(Wkv0, Wkv1);
    k_out<<<NN/8, 256>>>(node, Wm1, out);
}

// round 16
// speedup vs baseline: 1.9521x; 1.0667x over previous
#include <cuda_runtime.h>
#include <math.h>
#include <stdint.h>

#define NN 10000
#define NE 160000
#define HH 8
#define CPD 240
#define EPSLN 1e-5f
#define INV_SQRT2  0.70710678118654752f
#define INV_SQRT3  0.57735026918962576f
#define INV_SQRT32 0.17677669529663689f
#define INV_SQRT48 0.14433756729740643f
#define F_QK0 (1.0f/48.0f)
#define F_QK1 0.018042195912175804f
#define INV16 0.0625f
#define INV_SQRT128 0.08838834764831845f
#define GRID_CSR 296

__device__ float g_SD[NN*160];
__device__ __align__(16) float g_QK[(size_t)NN*HH*CPD];   // [n][j<240][h<8]
__device__ __align__(16) float g_CP[(size_t)NE*256];      // dst-slot order
__device__ float g_LG[(size_t)NE*8];                      // dst-slot order
__device__ int   g_CNTS[NN], g_CNTD[NN];
__device__ int   g_OFFS[NN+1], g_OFFD[NN+1];
__device__ int   g_CURS[NN], g_CURD[NN];
__device__ int   g_SEID[NE];
__device__ int   g_POS[NE];
__device__ __align__(16) float g_MSG[NN*640];
__device__ __align__(16) float g_W0T[256*48];    // key half Wkv0, [col][c]
__device__ __align__(16) float g_W1T[128*64];    // key half Wkv1, [col][u]
__device__ __align__(16) float g_Wm0P[256*64];   // [i][lane][{a0,a1}]
__device__ int   g_barA, g_barB, g_barC, g_barD;

__device__ __forceinline__ float warp_sum(float v) {
    #pragma unroll
    for (int o = 16; o; o >>= 1) v += __shfl_xor_sync(0xffffffffu, v, o);
    return v;
}
__device__ __forceinline__ void fma4(float4& a, float s, const float4 w) {
    a.x = fmaf(s, w.x, a.x); a.y = fmaf(s, w.y, a.y);
    a.z = fmaf(s, w.z, a.z); a.w = fmaf(s, w.w, a.w);
}
__device__ __forceinline__ void grid_bar(int* bar, int target) {
    __syncthreads();
    if (threadIdx.x == 0) {
        __threadfence();
        atomicAdd(bar, 1);
        while (*(volatile int*)bar < target) { }
    }
    __syncthreads();
    __threadfence();
}

__global__ void k_nop() { }

// fused: weight transposes + zero counters -> histogram -> dual scan -> bucket
__global__ void k_csr(const int* __restrict__ ei,
                      const float* __restrict__ Wkv0, const float* __restrict__ Wkv1,
                      const float* __restrict__ Wm0) {
    int tid = threadIdx.x;
    int gtid = blockIdx.x * 256 + tid;

    for (int t = gtid; t < 12288; t += GRID_CSR*256) {
        int c = t / 256, col = t % 256;
        g_W0T[col*48 + c] = Wkv0[c*512 + col];
    }
    for (int t = gtid; t < 8192; t += GRID_CSR*256) {
        int u = t / 128, col = t % 128;
        g_W1T[col*64 + u] = Wkv1[u*256 + col];
    }
    for (int t = gtid; t < 16384; t += GRID_CSR*256) {
        int i = t / 64, r = t % 64, ln = r / 2, sel = r % 2;
        g_Wm0P[t] = Wm0[i*64 + (sel ? 32 + ln : ln)];
    }

    for (int i = gtid; i < NN; i += GRID_CSR*256) { g_CNTS[i] = 0; g_CNTD[i] = 0; }
    grid_bar(&g_barA, GRID_CSR);

    for (int e = gtid; e < NE; e += GRID_CSR*256) {
        atomicAdd(&g_CNTS[__ldg(&ei[e])], 1);
        atomicAdd(&g_CNTD[__ldg(&ei[NE + e])], 1);
    }
    grid_bar(&g_barB, GRID_CSR);

    if (blockIdx.x < 2) {
        const int* cnt = (blockIdx.x == 0) ? g_CNTS : g_CNTD;
        int* off = (blockIdx.x == 0) ? g_OFFS : g_OFFD;
        int* cur = (blockIdx.x == 0) ? g_CURS : g_CURD;
        __shared__ int swt[8], swe[8];
        int w = tid >> 5, l = tid & 31;
        int base = tid * 40;
        int loc[40];
        int s = 0;
        #pragma unroll
        for (int i = 0; i < 40; i++) {
            int idx = base + i;
            int c = (idx < NN) ? cnt[idx] : 0;
            loc[i] = s; s += c;
        }
        int incl = s;
        #pragma unroll
        for (int o = 1; o < 32; o <<= 1) {
            int v = __shfl_up_sync(0xffffffffu, incl, o);
            if (l >= o) incl += v;
        }
        if (l == 31) swt[w] = incl;
        __syncthreads();
        if (w == 0) {
            int v = (l < 8) ? swt[l] : 0;
            int iv = v;
            #pragma unroll
            for (int o = 1; o < 8; o <<= 1) {
                int u = __shfl_up_sync(0xffffffffu, iv, o);
                if (l >= o) iv += u;
            }
            if (l < 8) swe[l] = iv - v;
        }
        __syncthreads();
        int excl = incl - s + swe[w];
        #pragma unroll
        for (int i = 0; i < 40; i++) {
            int idx = base + i;
            if (idx < NN) { int o2 = excl + loc[i]; off[idx] = o2; cur[idx] = o2; }
        }
        if (tid == 255) off[NN] = excl + s;
    }
    grid_bar(&g_barC, GRID_CSR);

    for (int e = gtid; e < NE; e += GRID_CSR*256) {
        int src = __ldg(&ei[e]), dst = __ldg(&ei[NE + e]);
        g_SEID[atomicAdd(&g_CURS[src], 1)] = e;
        g_POS[e] = atomicAdd(&g_CURD[dst], 1);
    }
    __syncthreads();
    if (tid == 0) {
        __threadfence();
        int old = atomicAdd(&g_barD, 1);
        if (old == GRID_CSR - 1) { g_barA = 0; g_barB = 0; g_barC = 0; g_barD = 0; }
    }
}

// per-node-pair warp: weights loaded once feed both nodes (R13 proven)
__global__ void __launch_bounds__(256, 3)
k_node(const float* __restrict__ node,
       const float* __restrict__ g0, const float* __restrict__ g1,
       const float* __restrict__ Wq0, const float* __restrict__ Wq1,
       const float* __restrict__ Ws0, const float* __restrict__ Ws1,
       const float* __restrict__ Wd0, const float* __restrict__ Wd1) {
    __shared__ float scratch[8][1600];
    int warp = threadIdx.x >> 5, lane = threadIdx.x & 31;
    float* wb  = scratch[warp];
    float* h0s = wb;          // [p][64]
    float* h1s = wb + 128;    // [p][96]
    float* q0s = wb + 320;    // [p][256]
    float* q1s = wb + 832;    // [p][384]

    int n0 = blockIdx.x * 16 + warp * 2;

    #pragma unroll
    for (int p = 0; p < 2; p++) {
        int n = n0 + p;
        const float* nr = node + (size_t)n * 160;
        float e0 = nr[lane], e1 = nr[32 + lane];
        float mu = warp_sum(e0 + e1) * (1.0f/64.0f);
        float var = warp_sum((e0-mu)*(e0-mu) + (e1-mu)*(e1-mu)) * (1.0f/64.0f);
        float rs0 = rsqrtf(var + EPSLN);
        h0s[p*64 + lane]    = (e0-mu)*rs0*__ldg(&g0[lane]);
        h0s[p*64 + 32+lane] = (e1-mu)*rs0*__ldg(&g0[32+lane]);
        float t0 = nr[64+lane], t1 = nr[96+lane], t2 = nr[128+lane];
        float vn = warp_sum(t0*t0 + t1*t1 + t2*t2) * (1.0f/32.0f);
        float rs1 = rsqrtf(vn + EPSLN);
        h1s[p*96 + lane]    = t0*rs1*__ldg(&g1[lane/3]);
        h1s[p*96 + 32+lane] = t1*rs1*__ldg(&g1[(32+lane)/3]);
        h1s[p*96 + 64+lane] = t2*rs1*__ldg(&g1[(64+lane)/3]);
    }
    __syncwarp();

    {
        float a0 = 0.f, b0 = 0.f, a1 = 0.f, b1 = 0.f;
        #pragma unroll
        for (int i = 0; i < 64; i++) {
            float ws = __ldg(&Ws0[i*32 + lane]);
            float wd = __ldg(&Wd0[i*32 + lane]);
            float hA = h0s[i], hB = h0s[64 + i];
            a0 = fmaf(hA, ws, a0); b0 = fmaf(hA, wd, b0);
            a1 = fmaf(hB, ws, a1); b1 = fmaf(hB, wd, b1);
        }
        g_SD[(size_t)n0*160 + lane]          = a0 * 0.125f;
        g_SD[(size_t)n0*160 + 80 + lane]     = b0 * 0.125f;
        g_SD[(size_t)(n0+1)*160 + lane]      = a1 * 0.125f;
        g_SD[(size_t)(n0+1)*160 + 80 + lane] = b1 * 0.125f;
    }
    #pragma unroll
    for (int rep = 0; rep < 2; rep++) {
        int j = rep*32 + lane;
        if (j < 48) {
            int v_ = j/3, c_ = j%3;
            float a0 = 0.f, b0 = 0.f, a1 = 0.f, b1 = 0.f;
            #pragma unroll
            for (int u = 0; u < 32; u++) {
                float ws = __ldg(&Ws1[u*16 + v_]);
                float wd = __ldg(&Wd1[u*16 + v_]);
                float hA = h1s[u*3 + c_], hB = h1s[96 + u*3 + c_];
                a0 = fmaf(hA, ws, a0); b0 = fmaf(hA, wd, b0);
                a1 = fmaf(hB, ws, a1); b1 = fmaf(hB, wd, b1);
            }
            g_SD[(size_t)n0*160 + 32 + j]       = a0 * INV_SQRT32;
            g_SD[(size_t)n0*160 + 112 + j]      = b0 * INV_SQRT32;
            g_SD[(size_t)(n0+1)*160 + 32 + j]   = a1 * INV_SQRT32;
            g_SD[(size_t)(n0+1)*160 + 112 + j]  = b1 * INV_SQRT32;
        }
    }
    #pragma unroll
    for (int h = 0; h < 8; h++) {
        float a0 = 0.f, a1 = 0.f;
        #pragma unroll
        for (int i = 0; i < 64; i++) {
            float w = __ldg(&Wq0[i*256 + h*32 + lane]);
            a0 = fmaf(h0s[i], w, a0);
            a1 = fmaf(h0s[64 + i], w, a1);
        }
        q0s[h*32 + lane]       = a0 * 0.125f;
        q0s[256 + h*32 + lane] = a1 * 0.125f;
    }
    #pragma unroll
    for (int k = 0; k < 12; k++) {
        int j = k*32 + lane;
        int h = j/48, r = j%48, v_ = r/3, c_ = r%3;
        float a0 = 0.f, a1 = 0.f;
        #pragma unroll
        for (int u = 0; u < 32; u++) {
            float w = __ldg(&Wq1[u*128 + h*16 + v_]);
            a0 = fmaf(h1s[u*3 + c_], w, a0);
            a1 = fmaf(h1s[96 + u*3 + c_], w, a1);
        }
        q1s[j]       = a0 * INV_SQRT32;
        q1s[384 + j] = a1 * INV_SQRT32;
    }
    __syncwarp();

    float* qk0n = g_QK + (size_t)n0 * (HH*CPD);
    float* qk1n = g_QK + (size_t)(n0+1) * (HH*CPD);
    #pragma unroll
    for (int k = 0; k < 12; k++) {
        int j = k*32 + lane;
        int h = j/48, c = j%48;
        float a0 = 0.f, a1 = 0.f;
        #pragma unroll
        for (int m = 0; m < 32; m++) {
            float w = __ldg(&g_W0T[(h*32+m)*48 + c]);
            a0 = fmaf(q0s[h*32 + m], w, a0);
            a1 = fmaf(q0s[256 + h*32 + m], w, a1);
        }
        qk0n[c*8 + h] = a0 * F_QK0;
        qk1n[c*8 + h] = a1 * F_QK0;
    }
    #pragma unroll
    for (int k = 0; k < 48; k++) {
        int j = k*32 + lane;
        int h = j/192, cart = (j/64)%3, u = j%64;
        float a0 = 0.f, a1 = 0.f;
        #pragma unroll
        for (int v_ = 0; v_ < 16; v_++) {
            float w = __ldg(&g_W1T[(h*16+v_)*64 + u]);
            a0 = fmaf(q1s[h*48 + v_*3 + cart], w, a0);
            a1 = fmaf(q1s[384 + h*48 + v_*3 + cart], w, a1);
        }
        qk0n[(48 + cart*64 + u)*8 + h] = a0 * F_QK1;
        qk1n[(48 + cart*64 + u)*8 + h] = a1 * F_QK1;
    }
}

// build 240-dim tensor-product vector for one edge (warp-cooperative)
__device__ __forceinline__ void build_cp(int e, int src, int dst,
                                         const float* __restrict__ rbf,
                                         const float* __restrict__ rsh,
                                         const float* __restrict__ Ws,
                                         float* wb, float* CP, int lane) {
    float* rb  = wb;
    float* ys  = wb + 16;
    float* x0s = wb + 20;
    float* x1s = wb + 52;
    if (lane < 16) rb[lane] = __ldg(&rbf[(size_t)e*16 + lane]);
    if (lane < 4)  ys[lane] = __ldg(&rsh[(size_t)e*4 + lane]);
    x0s[lane] = __ldg(&g_SD[(size_t)src*160 + lane]) + __ldg(&g_SD[(size_t)dst*160 + 80 + lane]);
    x1s[lane] = __ldg(&g_SD[(size_t)src*160 + 32 + lane]) + __ldg(&g_SD[(size_t)dst*160 + 112 + lane]);
    if (lane < 16)
        x1s[32+lane] = __ldg(&g_SD[(size_t)src*160 + 64 + lane]) + __ldg(&g_SD[(size_t)dst*160 + 144 + lane]);
    __syncwarp();

    float y0 = ys[0], y1x = ys[1], y1y = ys[2], y1z = ys[3];
    #define WCH(J, OUT) { float _a = 0.f; _Pragma("unroll") \
        for (int _k = 0; _k < 16; _k++) _a = fmaf(rb[_k], Ws[_k*112 + (J)], _a); OUT = _a; }

    { float w; WCH(lane, w); CP[lane] = w * x0s[lane] * y0; }
    if (lane < 16) {
        float w; WCH(32 + lane, w);
        float d = x1s[lane*3]*y1x + x1s[lane*3+1]*y1y + x1s[lane*3+2]*y1z;
        CP[32 + lane] = w * d * INV_SQRT3;
    }
    { float w; WCH(48 + lane, w);
      float xv = w * x0s[lane];
      CP[48 + lane]       = xv * y1x;
      CP[48 + 64 + lane]  = xv * y1y;
      CP[48 + 128 + lane] = xv * y1z; }
    if (lane < 16) {
        float w; WCH(80 + lane, w);
        float wy = w * y0;
        CP[48 + 32 + lane]       = wy * x1s[lane*3];
        CP[48 + 64 + 32 + lane]  = wy * x1s[lane*3+1];
        CP[48 + 128 + 32 + lane] = wy * x1s[lane*3+2];
    } else {
        int t = lane - 16;
        float w; WCH(96 + t, w);
        w *= INV_SQRT2;
        float ax = x1s[t*3], ay = x1s[t*3+1], az = x1s[t*3+2];
        CP[48 + 48 + t]       = w * (ay*y1z - az*y1y);
        CP[48 + 64 + 48 + t]  = w * (az*y1x - ax*y1z);
        CP[48 + 128 + 48 + t] = w * (ax*y1y - ay*y1x);
    }
    #undef WCH
    __syncwarp();
}

// per-src-node warp: chunks of 2 out-edges share one pass over QK[src] (R13 loop)
__global__ void __launch_bounds__(256, 4)
k_edge(const float* __restrict__ rbf, const float* __restrict__ rsh,
       const int* __restrict__ ei, const float* __restrict__ Wrbf) {
    __shared__ float sW[16*112];
    __shared__ float wbuf[8][112];
    __shared__ __align__(16) float cps[8][480];
    int warp = threadIdx.x >> 5, lane = threadIdx.x & 31;
    for (int i = threadIdx.x; i < 16*112; i += 256) sW[i] = Wrbf[i];
    __syncthreads();

    int n = blockIdx.x * 8 + warp;
    int offs = g_OFFS[n];
    int degS = g_OFFS[n+1] - offs;
    const float* qkb = g_QK + (size_t)n * 1920;
    float* wb = wbuf[warp];
    float* CPB = cps[warp];

    for (int base = 0; base < degS; base += 2) {
        int cnt = min(2, degS - base);
        int eL = 0, slotL = 0;
        if (lane < cnt) { eL = __ldg(&g_SEID[offs + base + lane]); slotL = __ldg(&g_POS[eL]); }
        int ee[2], sl[2];
        #pragma unroll
        for (int i = 0; i < 2; i++) {
            ee[i] = __shfl_sync(0xffffffffu, eL, i);
            sl[i] = __shfl_sync(0xffffffffu, slotL, i);
        }
        for (int i = 0; i < cnt; i++) {
            int e = ee[i];
            int dst = __ldg(&ei[NE + e]);
            build_cp(e, n, dst, rbf, rsh, sW, wb, CPB + i*240, lane);
        }

        float acc[16];
        #pragma unroll
        for (int k = 0; k < 16; k++) acc[k] = 0.f;
        for (int j = lane; j < 240; j += 32) {
            const float4* p = (const float4*)(qkb + j*8);
            float4 qa = __ldg(p), qb = __ldg(p + 1);
            #pragma unroll
            for (int i = 0; i < 2; i++) {
                float cp = CPB[i*240 + j];
                acc[i*8+0] = fmaf(cp, qa.x, acc[i*8+0]);
                acc[i*8+1] = fmaf(cp, qa.y, acc[i*8+1]);
                acc[i*8+2] = fmaf(cp, qa.z, acc[i*8+2]);
                acc[i*8+3] = fmaf(cp, qa.w, acc[i*8+3]);
                acc[i*8+4] = fmaf(cp, qb.x, acc[i*8+4]);
                acc[i*8+5] = fmaf(cp, qb.y, acc[i*8+5]);
                acc[i*8+6] = fmaf(cp, qb.z, acc[i*8+6]);
                acc[i*8+7] = fmaf(cp, qb.w, acc[i*8+7]);
            }
        }
        #pragma unroll
        for (int o = 16; o; o >>= 1)
            #pragma unroll
            for (int k = 0; k < 16; k++) acc[k] += __shfl_xor_sync(0xffffffffu, acc[k], o);

        if (lane == 0) {
            #pragma unroll
            for (int i = 0; i < 2; i++) {
                if (i < cnt) {
                    float4* lg = (float4*)(g_LG + (size_t)sl[i]*8);
                    lg[0] = make_float4(acc[i*8+0], acc[i*8+1], acc[i*8+2], acc[i*8+3]);
                    lg[1] = make_float4(acc[i*8+4], acc[i*8+5], acc[i*8+6], acc[i*8+7]);
                }
            }
        }
        for (int i = 0; i < cnt; i++) {
            float4* dcp = (float4*)(g_CP + (size_t)sl[i]*256);
            const float4* scp = (const float4*)(CPB + i*240);
            dcp[lane] = scp[lane];
            if (lane < 28) dcp[32+lane] = scp[32+lane];
        }
    }
}

// per-node: softmax + attn-weighted CP (4-edge unroll) + value GEMM
__global__ void k_gather(const float* __restrict__ Wkv0, const float* __restrict__ Wkv1) {
    extern __shared__ float sg[];
    float* sWv0 = sg;             // [c<48][j<256]
    float* sWv1 = sg + 12288;     // [u<64][j<128]
    float* sST  = sg + 20480;     // 8 warps x 512
    float* sMZ  = sg + 24576;     // 8 warps x 16

    int warp = threadIdx.x >> 5, lane = threadIdx.x & 31;
    for (int i = threadIdx.x; i < 12288; i += 256) {
        int c = i >> 8, j = i & 255;
        sWv0[i] = Wkv0[c*512 + 256 + j];
    }
    for (int i = threadIdx.x; i < 8192; i += 256) {
        int u = i >> 7, j = i & 127;
        sWv1[i] = Wkv1[u*256 + 128 + j];
    }
    __syncthreads();

    int n = blockIdx.x * 8 + warp;
    int start = g_OFFD[n];
    int deg = g_OFFD[n+1] - start;

    int q = lane >> 3, h = lane & 7;
    float m = -INFINITY;
    for (int i = q; i < deg; i += 4)
        m = fmaxf(m, __ldg(&g_LG[(size_t)(start+i)*8 + h]));
    m = fmaxf(m, __shfl_xor_sync(0xffffffffu, m, 8));
    m = fmaxf(m, __shfl_xor_sync(0xffffffffu, m, 16));
    float z = 0.f;
    for (int i = q; i < deg; i += 4)
        z += __expf(__ldg(&g_LG[(size_t)(start+i)*8 + h]) - m);
    z += __shfl_xor_sync(0xffffffffu, z, 8);
    z += __shfl_xor_sync(0xffffffffu, z, 16);
    float* mz = sMZ + warp*16;
    if (lane < 8) { mz[lane] = m; mz[8 + lane] = 1.f / (z + 1e-16f); }
    __syncwarp();

    float4 aA[8], aB[8];
    #pragma unroll
    for (int hh = 0; hh < 8; hh++) { aA[hh] = make_float4(0,0,0,0); aB[hh] = make_float4(0,0,0,0); }
    for (int i = 0; i < deg; i += 4) {
        int ss[4];
        float att[4] = {0.f, 0.f, 0.f, 0.f};
        #pragma unroll
        for (int k = 0; k < 4; k++) ss[k] = (i + k < deg) ? (start + i + k) : start + i;
        if (lane < 8) {
            att[0] = __expf(__ldg(&g_LG[(size_t)ss[0]*8 + lane]) - mz[lane]) * mz[8 + lane];
            if (i + 1 < deg) att[1] = __expf(__ldg(&g_LG[(size_t)ss[1]*8 + lane]) - mz[lane]) * mz[8 + lane];
            if (i + 2 < deg) att[2] = __expf(__ldg(&g_LG[(size_t)ss[2]*8 + lane]) - mz[lane]) * mz[8 + lane];
            if (i + 3 < deg) att[3] = __expf(__ldg(&g_LG[(size_t)ss[3]*8 + lane]) - mz[lane]) * mz[8 + lane];
        }
        float4 ca[4], cb[4];
        #pragma unroll
        for (int k = 0; k < 4; k++) {
            const float4* cp = (const float4*)(g_CP + (size_t)ss[k]*256);
            ca[k] = __ldg(&cp[lane]);
            cb[k] = (lane < 28) ? __ldg(&cp[32 + lane]) : make_float4(0,0,0,0);
        }
        #pragma unroll
        for (int hh = 0; hh < 8; hh++) {
            #pragma unroll
            for (int k = 0; k < 4; k++) {
                float a = __shfl_sync(0xffffffffu, att[k], hh);
                fma4(aA[hh], a, ca[k]);
                fma4(aB[hh], a, cb[k]);
            }
        }
    }

    float* st = sST + warp*512;
    float* mrow = g_MSG + (size_t)n * 640;
    #pragma unroll
    for (int p = 0; p < 4; p++) {
        int h0 = 2*p, h1 = 2*p + 1;
        ((float4*)st)[lane]      = aA[h0];
        ((float4*)st)[32 + lane] = aB[h0];
        ((float4*)st)[64 + lane] = aA[h1];
        ((float4*)st)[96 + lane] = aB[h1];
        __syncwarp();

        float a0 = 0.f, a1 = 0.f;
        #pragma unroll 4
        for (int c = 0; c < 48; c++) {
            a0 = fmaf(st[c],       sWv0[c*256 + h0*32 + lane], a0);
            a1 = fmaf(st[256 + c], sWv0[c*256 + h1*32 + lane], a1);
        }
        mrow[h0*80 + lane] = a0 * INV_SQRT48;
        mrow[h1*80 + lane] = a1 * INV_SQRT48;

        int hsel = (lane < 16) ? h0 : h1;
        int v_ = lane & 15;
        const float* stv = st + ((lane < 16) ? 0 : 256) + 48;
        float c0 = 0.f, c1 = 0.f, c2 = 0.f;
        #pragma unroll 4
        for (int u = 0; u < 64; u++) {
            float w = sWv1[u*128 + hsel*16 + v_];
            c0 = fmaf(stv[u],       w, c0);
            c1 = fmaf(stv[64 + u],  w, c1);
            c2 = fmaf(stv[128 + u], w, c2);
        }
        mrow[hsel*80 + 32 + v_*3 + 0] = c0 * 0.125f;
        mrow[hsel*80 + 32 + v_*3 + 1] = c1 * 0.125f;
        mrow[hsel*80 + 32 + v_*3 + 2] = c2 * 0.125f;
        __syncwarp();
    }
}

// paired: each warp handles 2 nodes so weight loads amortize
__global__ void __launch_bounds__(256, 3)
k_out(const float* __restrict__ node,
      const float* __restrict__ Wm1,
      float* __restrict__ out) {
    __shared__ float msgs_all[8][1280];
    int warp = threadIdx.x >> 5, lane = threadIdx.x & 31;
    int n0 = blockIdx.x * 16 + warp * 2;
    float* msgs = msgs_all[warp];
    for (int j = lane; j < 640; j += 32) {
        msgs[j]       = g_MSG[(size_t)n0*640 + j];
        msgs[640 + j] = g_MSG[(size_t)(n0+1)*640 + j];
    }
    __syncwarp();

    const float* nr0 = node + (size_t)n0 * 160;
    const float* nr1 = node + (size_t)(n0+1) * 160;
    float* or0 = out + (size_t)n0 * 160;
    float* or1 = out + (size_t)(n0+1) * 160;

    float a0 = 0.f, a1 = 0.f, a2 = 0.f, a3 = 0.f;
    #pragma unroll 8
    for (int i = 0; i < 256; i++) {
        int mo = (i >> 5)*80 + (i & 31);
        float m0 = msgs[mo], m1 = msgs[640 + mo];
        float2 w = __ldg((const float2*)(g_Wm0P + i*64 + lane*2));
        a0 = fmaf(m0, w.x, a0); a1 = fmaf(m0, w.y, a1);
        a2 = fmaf(m1, w.x, a2); a3 = fmaf(m1, w.y, a3);
    }
    or0[lane]      = nr0[lane]      + a0 * INV16;
    or0[32 + lane] = nr0[32 + lane] + a1 * INV16;
    or1[lane]      = nr1[lane]      + a2 * INV16;
    or1[32 + lane] = nr1[32 + lane] + a3 * INV16;

    float c00 = 0.f, c01 = 0.f, c02 = 0.f;
    float c10 = 0.f, c11 = 0.f, c12 = 0.f;
    #pragma unroll 8
    for (int u = 0; u < 128; u++) {
        int hh = u >> 4, v_ = u & 15;
        float w = __ldg(&Wm1[u*32 + lane]);
        int mo = hh*80 + 32 + v_*3;
        const float* mp0 = msgs + mo;
        const float* mp1 = msgs + 640 + mo;
        c00 = fmaf(mp0[0], w, c00); c01 = fmaf(mp0[1], w, c01); c02 = fmaf(mp0[2], w, c02);
        c10 = fmaf(mp1[0], w, c10); c11 = fmaf(mp1[1], w, c11); c12 = fmaf(mp1[2], w, c12);
    }
    or0[64 + lane*3 + 0] = nr0[64 + lane*3 + 0] + c00 * INV_SQRT128;
    or0[64 + lane*3 + 1] = nr0[64 + lane*3 + 1] + c01 * INV_SQRT128;
    or0[64 + lane*3 + 2] = nr0[64 + lane*3 + 2] + c02 * INV_SQRT128;
    or1[64 + lane*3 + 0] = nr1[64 + lane*3 + 0] + c10 * INV_SQRT128;
    or1[64 + lane*3 + 1] = nr1[64 + lane*3 + 1] + c11 * INV_SQRT128;
    or1[64 + lane*3 + 2] = nr1[64 + lane*3 + 2] + c12 * INV_SQRT128;
}

extern "C" void kernel_launch(void* const* d_in, const int* in_sizes, int n_in,
                              void* d_out, int out_size) {
    const float* node = (const float*)d_in[0];
    const float* rbf  = (const float*)d_in[1];
    const float* rsh  = (const float*)d_in[2];
    const int*   ei   = (const int*)d_in[3];
    const float* g0   = (const float*)d_in[4];
    const float* g1   = (const float*)d_in[5];
    const float* Wq0  = (const float*)d_in[6];
    const float* Wq1  = (const float*)d_in[7];
    const float* Ws0  = (const float*)d_in[8];
    const float* Ws1  = (const float*)d_in[9];
    const float* Wd0  = (const float*)d_in[10];
    const float* Wd1  = (const float*)d_in[11];
    const float* Wrbf = (const float*)d_in[12];
    const float* Wkv0 = (const float*)d_in[13];
    const float* Wkv1 = (const float*)d_in[14];
    const float* Wm0  = (const float*)d_in[15];
    const float* Wm1  = (const float*)d_in[16];
    float* out = (float*)d_out;

    cudaFuncSetAttribute(k_gather, cudaFuncAttributeMaxDynamicSharedMemorySize, 98816);

    k_csr<<<GRID_CSR, 256>>>(ei, Wkv0, Wkv1, Wm0);
    k_node<<<NN/16, 256>>>(node, g0, g1, Wq0, Wq1, Ws0, Ws1, Wd0, Wd1);
    k_nop<<<1, 32>>>();
    k_edge<<<NN/8, 256>>>(rbf, rsh, ei, Wrbf);
    k_gather<<<NN/8, 256, 98816>>>(Wkv0, Wkv1);
    k_out<<<NN/16, 256>>>(node, Wm1, out);
}

// round 17
// speedup vs baseline: 2.0521x; 1.0512x over previous
#include <cuda_runtime.h>
#include <math.h>
#include <stdint.h>

#define NN 10000
#define NE 160000
#define HH 8
#define CPD 240
#define EPSLN 1e-5f
#define INV_SQRT2  0.70710678118654752f
#define INV_SQRT3  0.57735026918962576f
#define INV_SQRT32 0.17677669529663689f
#define INV_SQRT48 0.14433756729740643f
#define F_QK0 (1.0f/48.0f)
#define F_QK1 0.018042195912175804f
#define INV16 0.0625f
#define INV_SQRT128 0.08838834764831845f
#define GRID_CSR 296

__device__ float g_SD[NN*160];
__device__ __align__(16) float g_QK[(size_t)NN*HH*CPD];   // [n][j<240][h<8]
__device__ __align__(16) float g_CP[(size_t)NE*256];      // dst-slot order
__device__ float g_LG[(size_t)NE*8];                      // dst-slot order
__device__ int   g_CNTS[NN], g_CNTD[NN];
__device__ int   g_OFFS[NN+1], g_OFFD[NN+1];
__device__ int   g_CURS[NN], g_CURD[NN];
__device__ int   g_SEID[NE];
__device__ int   g_POS[NE];
__device__ __align__(16) float g_MSG[NN*640];
__device__ __align__(16) float g_W0T[256*48];    // key half Wkv0, [col][c]
__device__ __align__(16) float g_W1T[128*64];    // key half Wkv1, [col][u]
__device__ __align__(16) float g_Wm0P[256*64];   // [i][lane][{a0,a1}]
__device__ int   g_barA, g_barB, g_barC, g_barD;

__device__ __forceinline__ float warp_sum(float v) {
    #pragma unroll
    for (int o = 16; o; o >>= 1) v += __shfl_xor_sync(0xffffffffu, v, o);
    return v;
}
__device__ __forceinline__ void fma4(float4& a, float s, const float4 w) {
    a.x = fmaf(s, w.x, a.x); a.y = fmaf(s, w.y, a.y);
    a.z = fmaf(s, w.z, a.z); a.w = fmaf(s, w.w, a.w);
}
__device__ __forceinline__ void grid_bar(int* bar, int target) {
    __syncthreads();
    if (threadIdx.x == 0) {
        __threadfence();
        atomicAdd(bar, 1);
        while (*(volatile int*)bar < target) { }
    }
    __syncthreads();
    __threadfence();
}

__global__ void k_nop() { }

// fused: weight transposes + zero counters -> histogram -> dual scan -> bucket
__global__ void k_csr(const int* __restrict__ ei,
                      const float* __restrict__ Wkv0, const float* __restrict__ Wkv1,
                      const float* __restrict__ Wm0) {
    int tid = threadIdx.x;
    int gtid = blockIdx.x * 256 + tid;

    for (int t = gtid; t < 12288; t += GRID_CSR*256) {
        int c = t / 256, col = t % 256;
        g_W0T[col*48 + c] = Wkv0[c*512 + col];
    }
    for (int t = gtid; t < 8192; t += GRID_CSR*256) {
        int u = t / 128, col = t % 128;
        g_W1T[col*64 + u] = Wkv1[u*256 + col];
    }
    for (int t = gtid; t < 16384; t += GRID_CSR*256) {
        int i = t / 64, r = t % 64, ln = r / 2, sel = r % 2;
        g_Wm0P[t] = Wm0[i*64 + (sel ? 32 + ln : ln)];
    }

    for (int i = gtid; i < NN; i += GRID_CSR*256) { g_CNTS[i] = 0; g_CNTD[i] = 0; }
    grid_bar(&g_barA, GRID_CSR);

    for (int e = gtid; e < NE; e += GRID_CSR*256) {
        atomicAdd(&g_CNTS[__ldg(&ei[e])], 1);
        atomicAdd(&g_CNTD[__ldg(&ei[NE + e])], 1);
    }
    grid_bar(&g_barB, GRID_CSR);

    if (blockIdx.x < 2) {
        const int* cnt = (blockIdx.x == 0) ? g_CNTS : g_CNTD;
        int* off = (blockIdx.x == 0) ? g_OFFS : g_OFFD;
        int* cur = (blockIdx.x == 0) ? g_CURS : g_CURD;
        __shared__ int swt[8], swe[8];
        int w = tid >> 5, l = tid & 31;
        int base = tid * 40;
        int loc[40];
        int s = 0;
        #pragma unroll
        for (int i = 0; i < 40; i++) {
            int idx = base + i;
            int c = (idx < NN) ? cnt[idx] : 0;
            loc[i] = s; s += c;
        }
        int incl = s;
        #pragma unroll
        for (int o = 1; o < 32; o <<= 1) {
            int v = __shfl_up_sync(0xffffffffu, incl, o);
            if (l >= o) incl += v;
        }
        if (l == 31) swt[w] = incl;
        __syncthreads();
        if (w == 0) {
            int v = (l < 8) ? swt[l] : 0;
            int iv = v;
            #pragma unroll
            for (int o = 1; o < 8; o <<= 1) {
                int u = __shfl_up_sync(0xffffffffu, iv, o);
                if (l >= o) iv += u;
            }
            if (l < 8) swe[l] = iv - v;
        }
        __syncthreads();
        int excl = incl - s + swe[w];
        #pragma unroll
        for (int i = 0; i < 40; i++) {
            int idx = base + i;
            if (idx < NN) { int o2 = excl + loc[i]; off[idx] = o2; cur[idx] = o2; }
        }
        if (tid == 255) off[NN] = excl + s;
    }
    grid_bar(&g_barC, GRID_CSR);

    for (int e = gtid; e < NE; e += GRID_CSR*256) {
        int src = __ldg(&ei[e]), dst = __ldg(&ei[NE + e]);
        g_SEID[atomicAdd(&g_CURS[src], 1)] = e;
        g_POS[e] = atomicAdd(&g_CURD[dst], 1);
    }
    __syncthreads();
    if (tid == 0) {
        __threadfence();
        int old = atomicAdd(&g_barD, 1);
        if (old == GRID_CSR - 1) { g_barA = 0; g_barB = 0; g_barC = 0; g_barD = 0; }
    }
}

// per-node-pair warp: weights loaded once feed both nodes
__global__ void __launch_bounds__(256, 3)
k_node(const float* __restrict__ node,
       const float* __restrict__ g0, const float* __restrict__ g1,
       const float* __restrict__ Wq0, const float* __restrict__ Wq1,
       const float* __restrict__ Ws0, const float* __restrict__ Ws1,
       const float* __restrict__ Wd0, const float* __restrict__ Wd1) {
    __shared__ float scratch[8][1600];
    int warp = threadIdx.x >> 5, lane = threadIdx.x & 31;
    float* wb  = scratch[warp];
    float* h0s = wb;
    float* h1s = wb + 128;
    float* q0s = wb + 320;
    float* q1s = wb + 832;

    int n0 = blockIdx.x * 16 + warp * 2;

    #pragma unroll
    for (int p = 0; p < 2; p++) {
        int n = n0 + p;
        const float* nr = node + (size_t)n * 160;
        float e0 = nr[lane], e1 = nr[32 + lane];
        float mu = warp_sum(e0 + e1) * (1.0f/64.0f);
        float var = warp_sum((e0-mu)*(e0-mu) + (e1-mu)*(e1-mu)) * (1.0f/64.0f);
        float rs0 = rsqrtf(var + EPSLN);
        h0s[p*64 + lane]    = (e0-mu)*rs0*__ldg(&g0[lane]);
        h0s[p*64 + 32+lane] = (e1-mu)*rs0*__ldg(&g0[32+lane]);
        float t0 = nr[64+lane], t1 = nr[96+lane], t2 = nr[128+lane];
        float vn = warp_sum(t0*t0 + t1*t1 + t2*t2) * (1.0f/32.0f);
        float rs1 = rsqrtf(vn + EPSLN);
        h1s[p*96 + lane]    = t0*rs1*__ldg(&g1[lane/3]);
        h1s[p*96 + 32+lane] = t1*rs1*__ldg(&g1[(32+lane)/3]);
        h1s[p*96 + 64+lane] = t2*rs1*__ldg(&g1[(64+lane)/3]);
    }
    __syncwarp();

    {
        float a0 = 0.f, b0 = 0.f, a1 = 0.f, b1 = 0.f;
        #pragma unroll
        for (int i = 0; i < 64; i++) {
            float ws = __ldg(&Ws0[i*32 + lane]);
            float wd = __ldg(&Wd0[i*32 + lane]);
            float hA = h0s[i], hB = h0s[64 + i];
            a0 = fmaf(hA, ws, a0); b0 = fmaf(hA, wd, b0);
            a1 = fmaf(hB, ws, a1); b1 = fmaf(hB, wd, b1);
        }
        g_SD[(size_t)n0*160 + lane]          = a0 * 0.125f;
        g_SD[(size_t)n0*160 + 80 + lane]     = b0 * 0.125f;
        g_SD[(size_t)(n0+1)*160 + lane]      = a1 * 0.125f;
        g_SD[(size_t)(n0+1)*160 + 80 + lane] = b1 * 0.125f;
    }
    #pragma unroll
    for (int rep = 0; rep < 2; rep++) {
        int j = rep*32 + lane;
        if (j < 48) {
            int v_ = j/3, c_ = j%3;
            float a0 = 0.f, b0 = 0.f, a1 = 0.f, b1 = 0.f;
            #pragma unroll
            for (int u = 0; u < 32; u++) {
                float ws = __ldg(&Ws1[u*16 + v_]);
                float wd = __ldg(&Wd1[u*16 + v_]);
                float hA = h1s[u*3 + c_], hB = h1s[96 + u*3 + c_];
                a0 = fmaf(hA, ws, a0); b0 = fmaf(hA, wd, b0);
                a1 = fmaf(hB, ws, a1); b1 = fmaf(hB, wd, b1);
            }
            g_SD[(size_t)n0*160 + 32 + j]       = a0 * INV_SQRT32;
            g_SD[(size_t)n0*160 + 112 + j]      = b0 * INV_SQRT32;
            g_SD[(size_t)(n0+1)*160 + 32 + j]   = a1 * INV_SQRT32;
            g_SD[(size_t)(n0+1)*160 + 112 + j]  = b1 * INV_SQRT32;
        }
    }
    #pragma unroll
    for (int h = 0; h < 8; h++) {
        float a0 = 0.f, a1 = 0.f;
        #pragma unroll
        for (int i = 0; i < 64; i++) {
            float w = __ldg(&Wq0[i*256 + h*32 + lane]);
            a0 = fmaf(h0s[i], w, a0);
            a1 = fmaf(h0s[64 + i], w, a1);
        }
        q0s[h*32 + lane]       = a0 * 0.125f;
        q0s[256 + h*32 + lane] = a1 * 0.125f;
    }
    #pragma unroll
    for (int k = 0; k < 12; k++) {
        int j = k*32 + lane;
        int h = j/48, r = j%48, v_ = r/3, c_ = r%3;
        float a0 = 0.f, a1 = 0.f;
        #pragma unroll
        for (int u = 0; u < 32; u++) {
            float w = __ldg(&Wq1[u*128 + h*16 + v_]);
            a0 = fmaf(h1s[u*3 + c_], w, a0);
            a1 = fmaf(h1s[96 + u*3 + c_], w, a1);
        }
        q1s[j]       = a0 * INV_SQRT32;
        q1s[384 + j] = a1 * INV_SQRT32;
    }
    __syncwarp();

    float* qk0n = g_QK + (size_t)n0 * (HH*CPD);
    float* qk1n = g_QK + (size_t)(n0+1) * (HH*CPD);
    #pragma unroll
    for (int k = 0; k < 12; k++) {
        int j = k*32 + lane;
        int h = j/48, c = j%48;
        float a0 = 0.f, a1 = 0.f;
        #pragma unroll
        for (int m = 0; m < 32; m++) {
            float w = __ldg(&g_W0T[(h*32+m)*48 + c]);
            a0 = fmaf(q0s[h*32 + m], w, a0);
            a1 = fmaf(q0s[256 + h*32 + m], w, a1);
        }
        qk0n[c*8 + h] = a0 * F_QK0;
        qk1n[c*8 + h] = a1 * F_QK0;
    }
    #pragma unroll
    for (int k = 0; k < 48; k++) {
        int j = k*32 + lane;
        int h = j/192, cart = (j/64)%3, u = j%64;
        float a0 = 0.f, a1 = 0.f;
        #pragma unroll
        for (int v_ = 0; v_ < 16; v_++) {
            float w = __ldg(&g_W1T[(h*16+v_)*64 + u]);
            a0 = fmaf(q1s[h*48 + v_*3 + cart], w, a0);
            a1 = fmaf(q1s[384 + h*48 + v_*3 + cart], w, a1);
        }
        qk0n[(48 + cart*64 + u)*8 + h] = a0 * F_QK1;
        qk1n[(48 + cart*64 + u)*8 + h] = a1 * F_QK1;
    }
}

// build 240-dim tensor-product vector for one edge (warp-cooperative)
__device__ __forceinline__ void build_cp(int e, int src, int dst,
                                         const float* __restrict__ rbf,
                                         const float* __restrict__ rsh,
                                         const float* __restrict__ Ws,
                                         float* wb, float* CP, int lane) {
    float* rb  = wb;
    float* ys  = wb + 16;
    float* x0s = wb + 20;
    float* x1s = wb + 52;
    if (lane < 16) rb[lane] = __ldg(&rbf[(size_t)e*16 + lane]);
    if (lane < 4)  ys[lane] = __ldg(&rsh[(size_t)e*4 + lane]);
    x0s[lane] = __ldg(&g_SD[(size_t)src*160 + lane]) + __ldg(&g_SD[(size_t)dst*160 + 80 + lane]);
    x1s[lane] = __ldg(&g_SD[(size_t)src*160 + 32 + lane]) + __ldg(&g_SD[(size_t)dst*160 + 112 + lane]);
    if (lane < 16)
        x1s[32+lane] = __ldg(&g_SD[(size_t)src*160 + 64 + lane]) + __ldg(&g_SD[(size_t)dst*160 + 144 + lane]);
    __syncwarp();

    float y0 = ys[0], y1x = ys[1], y1y = ys[2], y1z = ys[3];
    #define WCH(J, OUT) { float _a = 0.f; _Pragma("unroll") \
        for (int _k = 0; _k < 16; _k++) _a = fmaf(rb[_k], Ws[_k*112 + (J)], _a); OUT = _a; }

    { float w; WCH(lane, w); CP[lane] = w * x0s[lane] * y0; }
    if (lane < 16) {
        float w; WCH(32 + lane, w);
        float d = x1s[lane*3]*y1x + x1s[lane*3+1]*y1y + x1s[lane*3+2]*y1z;
        CP[32 + lane] = w * d * INV_SQRT3;
    }
    { float w; WCH(48 + lane, w);
      float xv = w * x0s[lane];
      CP[48 + lane]       = xv * y1x;
      CP[48 + 64 + lane]  = xv * y1y;
      CP[48 + 128 + lane] = xv * y1z; }
    if (lane < 16) {
        float w; WCH(80 + lane, w);
        float wy = w * y0;
        CP[48 + 32 + lane]       = wy * x1s[lane*3];
        CP[48 + 64 + 32 + lane]  = wy * x1s[lane*3+1];
        CP[48 + 128 + 32 + lane] = wy * x1s[lane*3+2];
    } else {
        int t = lane - 16;
        float w; WCH(96 + t, w);
        w *= INV_SQRT2;
        float ax = x1s[t*3], ay = x1s[t*3+1], az = x1s[t*3+2];
        CP[48 + 48 + t]       = w * (ay*y1z - az*y1y);
        CP[48 + 64 + 48 + t]  = w * (az*y1x - ax*y1z);
        CP[48 + 128 + 48 + t] = w * (ax*y1y - ay*y1x);
    }
    #undef WCH
    __syncwarp();
}

// balanced: each warp owns 8 consecutive SEID pairs (16 edges).
// src-sorted order keeps QK L1 reuse; pairs straddling a src boundary
// take the (rare, warp-uniform) two-pass path.
__global__ void __launch_bounds__(256, 4)
k_edge(const float* __restrict__ rbf, const float* __restrict__ rsh,
       const int* __restrict__ ei, const float* __restrict__ Wrbf) {
    __shared__ float sW[16*112];
    __shared__ float wbuf[8][112];
    __shared__ __align__(16) float cps[8][480];
    int warp = threadIdx.x >> 5, lane = threadIdx.x & 31;
    for (int i = threadIdx.x; i < 16*112; i += 256) sW[i] = Wrbf[i];
    __syncthreads();

    int wid_g = blockIdx.x * 8 + warp;       // 0..9999
    float* wb = wbuf[warp];
    float* CPB = cps[warp];

    #pragma unroll 1
    for (int pp = 0; pp < 8; pp++) {
        int base = (wid_g * 8 + pp) * 2;
        int eL = 0, slotL = 0;
        if (lane < 2) { eL = __ldg(&g_SEID[base + lane]); slotL = __ldg(&g_POS[eL]); }
        int ee[2], sl[2], sr[2];
        #pragma unroll
        for (int i = 0; i < 2; i++) {
            ee[i] = __shfl_sync(0xffffffffu, eL, i);
            sl[i] = __shfl_sync(0xffffffffu, slotL, i);
        }
        sr[0] = __ldg(&ei[ee[0]]);
        sr[1] = __ldg(&ei[ee[1]]);
        #pragma unroll
        for (int i = 0; i < 2; i++) {
            int dst = __ldg(&ei[NE + ee[i]]);
            build_cp(ee[i], sr[i], dst, rbf, rsh, sW, wb, CPB + i*240, lane);
        }

        float acc[16];
        #pragma unroll
        for (int k = 0; k < 16; k++) acc[k] = 0.f;
        if (sr[0] == sr[1]) {
            const float* qkb = g_QK + (size_t)sr[0] * 1920;
            for (int j = lane; j < 240; j += 32) {
                const float4* p = (const float4*)(qkb + j*8);
                float4 qa = __ldg(p), qb = __ldg(p + 1);
                #pragma unroll
                for (int i = 0; i < 2; i++) {
                    float cp = CPB[i*240 + j];
                    acc[i*8+0] = fmaf(cp, qa.x, acc[i*8+0]);
                    acc[i*8+1] = fmaf(cp, qa.y, acc[i*8+1]);
                    acc[i*8+2] = fmaf(cp, qa.z, acc[i*8+2]);
                    acc[i*8+3] = fmaf(cp, qa.w, acc[i*8+3]);
                    acc[i*8+4] = fmaf(cp, qb.x, acc[i*8+4]);
                    acc[i*8+5] = fmaf(cp, qb.y, acc[i*8+5]);
                    acc[i*8+6] = fmaf(cp, qb.z, acc[i*8+6]);
                    acc[i*8+7] = fmaf(cp, qb.w, acc[i*8+7]);
                }
            }
        } else {
            #pragma unroll
            for (int i = 0; i < 2; i++) {
                const float* qkb = g_QK + (size_t)sr[i] * 1920;
                for (int j = lane; j < 240; j += 32) {
                    const float4* p = (const float4*)(qkb + j*8);
                    float4 qa = __ldg(p), qb = __ldg(p + 1);
                    float cp = CPB[i*240 + j];
                    acc[i*8+0] = fmaf(cp, qa.x, acc[i*8+0]);
                    acc[i*8+1] = fmaf(cp, qa.y, acc[i*8+1]);
                    acc[i*8+2] = fmaf(cp, qa.z, acc[i*8+2]);
                    acc[i*8+3] = fmaf(cp, qa.w, acc[i*8+3]);
                    acc[i*8+4] = fmaf(cp, qb.x, acc[i*8+4]);
                    acc[i*8+5] = fmaf(cp, qb.y, acc[i*8+5]);
                    acc[i*8+6] = fmaf(cp, qb.z, acc[i*8+6]);
                    acc[i*8+7] = fmaf(cp, qb.w, acc[i*8+7]);
                }
            }
        }
        #pragma unroll
        for (int o = 16; o; o >>= 1)
            #pragma unroll
            for (int k = 0; k < 16; k++) acc[k] += __shfl_xor_sync(0xffffffffu, acc[k], o);

        if (lane == 0) {
            #pragma unroll
            for (int i = 0; i < 2; i++) {
                float4* lg = (float4*)(g_LG + (size_t)sl[i]*8);
                lg[0] = make_float4(acc[i*8+0], acc[i*8+1], acc[i*8+2], acc[i*8+3]);
                lg[1] = make_float4(acc[i*8+4], acc[i*8+5], acc[i*8+6], acc[i*8+7]);
            }
        }
        #pragma unroll
        for (int i = 0; i < 2; i++) {
            float4* dcp = (float4*)(g_CP + (size_t)sl[i]*256);
            const float4* scp = (const float4*)(CPB + i*240);
            dcp[lane] = scp[lane];
            if (lane < 28) dcp[32+lane] = scp[32+lane];
        }
    }
}

// per-node: softmax + attn-weighted CP (4-edge unroll) + value GEMM
__global__ void k_gather(const float* __restrict__ Wkv0, const float* __restrict__ Wkv1) {
    extern __shared__ float sg[];
    float* sWv0 = sg;             // [c<48][j<256]
    float* sWv1 = sg + 12288;     // [u<64][j<128]
    float* sST  = sg + 20480;     // 8 warps x 512
    float* sMZ  = sg + 24576;     // 8 warps x 16

    int warp = threadIdx.x >> 5, lane = threadIdx.x & 31;
    for (int i = threadIdx.x; i < 12288; i += 256) {
        int c = i >> 8, j = i & 255;
        sWv0[i] = Wkv0[c*512 + 256 + j];
    }
    for (int i = threadIdx.x; i < 8192; i += 256) {
        int u = i >> 7, j = i & 127;
        sWv1[i] = Wkv1[u*256 + 128 + j];
    }
    __syncthreads();

    int n = blockIdx.x * 8 + warp;
    int start = g_OFFD[n];
    int deg = g_OFFD[n+1] - start;

    int q = lane >> 3, h = lane & 7;
    float m = -INFINITY;
    for (int i = q; i < deg; i += 4)
        m = fmaxf(m, __ldg(&g_LG[(size_t)(start+i)*8 + h]));
    m = fmaxf(m, __shfl_xor_sync(0xffffffffu, m, 8));
    m = fmaxf(m, __shfl_xor_sync(0xffffffffu, m, 16));
    float z = 0.f;
    for (int i = q; i < deg; i += 4)
        z += __expf(__ldg(&g_LG[(size_t)(start+i)*8 + h]) - m);
    z += __shfl_xor_sync(0xffffffffu, z, 8);
    z += __shfl_xor_sync(0xffffffffu, z, 16);
    float* mz = sMZ + warp*16;
    if (lane < 8) { mz[lane] = m; mz[8 + lane] = 1.f / (z + 1e-16f); }
    __syncwarp();

    float4 aA[8], aB[8];
    #pragma unroll
    for (int hh = 0; hh < 8; hh++) { aA[hh] = make_float4(0,0,0,0); aB[hh] = make_float4(0,0,0,0); }
    for (int i = 0; i < deg; i += 4) {
        int ss[4];
        float att[4] = {0.f, 0.f, 0.f, 0.f};
        #pragma unroll
        for (int k = 0; k < 4; k++) ss[k] = (i + k < deg) ? (start + i + k) : start + i;
        if (lane < 8) {
            att[0] = __expf(__ldg(&g_LG[(size_t)ss[0]*8 + lane]) - mz[lane]) * mz[8 + lane];
            if (i + 1 < deg) att[1] = __expf(__ldg(&g_LG[(size_t)ss[1]*8 + lane]) - mz[lane]) * mz[8 + lane];
            if (i + 2 < deg) att[2] = __expf(__ldg(&g_LG[(size_t)ss[2]*8 + lane]) - mz[lane]) * mz[8 + lane];
            if (i + 3 < deg) att[3] = __expf(__ldg(&g_LG[(size_t)ss[3]*8 + lane]) - mz[lane]) * mz[8 + lane];
        }
        float4 ca[4], cb[4];
        #pragma unroll
        for (int k = 0; k < 4; k++) {
            const float4* cp = (const float4*)(g_CP + (size_t)ss[k]*256);
            ca[k] = __ldg(&cp[lane]);
            cb[k] = (lane < 28) ? __ldg(&cp[32 + lane]) : make_float4(0,0,0,0);
        }
        #pragma unroll
        for (int hh = 0; hh < 8; hh++) {
            #pragma unroll
            for (int k = 0; k < 4; k++) {
                float a = __shfl_sync(0xffffffffu, att[k], hh);
                fma4(aA[hh], a, ca[k]);
                fma4(aB[hh], a, cb[k]);
            }
        }
    }

    float* st = sST + warp*512;
    float* mrow = g_MSG + (size_t)n * 640;
    #pragma unroll
    for (int p = 0; p < 4; p++) {
        int h0 = 2*p, h1 = 2*p + 1;
        ((float4*)st)[lane]      = aA[h0];
        ((float4*)st)[32 + lane] = aB[h0];
        ((float4*)st)[64 + lane] = aA[h1];
        ((float4*)st)[96 + lane] = aB[h1];
        __syncwarp();

        float a0 = 0.f, a1 = 0.f;
        #pragma unroll 4
        for (int c = 0; c < 48; c++) {
            a0 = fmaf(st[c],       sWv0[c*256 + h0*32 + lane], a0);
            a1 = fmaf(st[256 + c], sWv0[c*256 + h1*32 + lane], a1);
        }
        mrow[h0*80 + lane] = a0 * INV_SQRT48;
        mrow[h1*80 + lane] = a1 * INV_SQRT48;

        int hsel = (lane < 16) ? h0 : h1;
        int v_ = lane & 15;
        const float* stv = st + ((lane < 16) ? 0 : 256) + 48;
        float c0 = 0.f, c1 = 0.f, c2 = 0.f;
        #pragma unroll 4
        for (int u = 0; u < 64; u++) {
            float w = sWv1[u*128 + hsel*16 + v_];
            c0 = fmaf(stv[u],       w, c0);
            c1 = fmaf(stv[64 + u],  w, c1);
            c2 = fmaf(stv[128 + u], w, c2);
        }
        mrow[hsel*80 + 32 + v_*3 + 0] = c0 * 0.125f;
        mrow[hsel*80 + 32 + v_*3 + 1] = c1 * 0.125f;
        mrow[hsel*80 + 32 + v_*3 + 2] = c2 * 0.125f;
        __syncwarp();
    }
}

// paired: each warp handles 2 nodes so weight loads amortize
__global__ void __launch_bounds__(256, 3)
k_out(const float* __restrict__ node,
      const float* __restrict__ Wm1,
      float* __restrict__ out) {
    __shared__ float msgs_all[8][1280];
    int warp = threadIdx.x >> 5, lane = threadIdx.x & 31;
    int n0 = blockIdx.x * 16 + warp * 2;
    float* msgs = msgs_all[warp];
    for (int j = lane; j < 640; j += 32) {
        msgs[j]       = g_MSG[(size_t)n0*640 + j];
        msgs[640 + j] = g_MSG[(size_t)(n0+1)*640 + j];
    }
    __syncwarp();

    const float* nr0 = node + (size_t)n0 * 160;
    const float* nr1 = node + (size_t)(n0+1) * 160;
    float* or0 = out + (size_t)n0 * 160;
    float* or1 = out + (size_t)(n0+1) * 160;

    float a0 = 0.f, a1 = 0.f, a2 = 0.f, a3 = 0.f;
    #pragma unroll 8
    for (int i = 0; i < 256; i++) {
        int mo = (i >> 5)*80 + (i & 31);
        float m0 = msgs[mo], m1 = msgs[640 + mo];
        float2 w = __ldg((const float2*)(g_Wm0P + i*64 + lane*2));
        a0 = fmaf(m0, w.x, a0); a1 = fmaf(m0, w.y, a1);
        a2 = fmaf(m1, w.x, a2); a3 = fmaf(m1, w.y, a3);
    }
    or0[lane]      = nr0[lane]      + a0 * INV16;
    or0[32 + lane] = nr0[32 + lane] + a1 * INV16;
    or1[lane]      = nr1[lane]      + a2 * INV16;
    or1[32 + lane] = nr1[32 + lane] + a3 * INV16;

    float c00 = 0.f, c01 = 0.f, c02 = 0.f;
    float c10 = 0.f, c11 = 0.f, c12 = 0.f;
    #pragma unroll 8
    for (int u = 0; u < 128; u++) {
        int hh = u >> 4, v_ = u & 15;
        float w = __ldg(&Wm1[u*32 + lane]);
        int mo = hh*80 + 32 + v_*3;
        const float* mp0 = msgs + mo;
        const float* mp1 = msgs + 640 + mo;
        c00 = fmaf(mp0[0], w, c00); c01 = fmaf(mp0[1], w, c01); c02 = fmaf(mp0[2], w, c02);
        c10 = fmaf(mp1[0], w, c10); c11 = fmaf(mp1[1], w, c11); c12 = fmaf(mp1[2], w, c12);
    }
    or0[64 + lane*3 + 0] = nr0[64 + lane*3 + 0] + c00 * INV_SQRT128;
    or0[64 + lane*3 + 1] = nr0[64 + lane*3 + 1] + c01 * INV_SQRT128;
    or0[64 + lane*3 + 2] = nr0[64 + lane*3 + 2] + c02 * INV_SQRT128;
    or1[64 + lane*3 + 0] = nr1[64 + lane*3 + 0] + c10 * INV_SQRT128;
    or1[64 + lane*3 + 1] = nr1[64 + lane*3 + 1] + c11 * INV_SQRT128;
    or1[64 + lane*3 + 2] = nr1[64 + lane*3 + 2] + c12 * INV_SQRT128;
}

extern "C" void kernel_launch(void* const* d_in, const int* in_sizes, int n_in,
                              void* d_out, int out_size) {
    const float* node = (const float*)d_in[0];
    const float* rbf  = (const float*)d_in[1];
    const float* rsh  = (const float*)d_in[2];
    const int*   ei   = (const int*)d_in[3];
    const float* g0   = (const float*)d_in[4];
    const float* g1   = (const float*)d_in[5];
    const float* Wq0  = (const float*)d_in[6];
    const float* Wq1  = (const float*)d_in[7];
    const float* Ws0  = (const float*)d_in[8];
    const float* Ws1  = (const float*)d_in[9];
    const float* Wd0  = (const float*)d_in[10];
    const float* Wd1  = (const float*)d_in[11];
    const float* Wrbf = (const float*)d_in[12];
    const float* Wkv0 = (const float*)d_in[13];
    const float* Wkv1 = (const float*)d_in[14];
    const float* Wm0  = (const float*)d_in[15];
    const float* Wm1  = (const float*)d_in[16];
    float* out = (float*)d_out;

    cudaFuncSetAttribute(k_gather, cudaFuncAttributeMaxDynamicSharedMemorySize, 98816);

    k_csr<<<GRID_CSR, 256>>>(ei, Wkv0, Wkv1, Wm0);
    k_node<<<NN/16, 256>>>(node, g0, g1, Wq0, Wq1, Ws0, Ws1, Wd0, Wd1);
    k_nop<<<1, 32>>>();
    k_edge<<<NN/8, 256>>>(rbf, rsh, ei, Wrbf);
    k_gather<<<NN/8, 256, 98816>>>(Wkv0, Wkv1);
    k_out<<<NN/16, 256>>>(node, Wm1, out);
}